// round 12
// baseline (speedup 1.0000x reference)
#include <cuda_runtime.h>
#include <math.h>

// Problem constants
constexpr int S   = 1024;   // tokens
constexpr int H   = 2048;   // hidden
constexpr int NH  = 16;     // q heads
constexpr int NKV = 4;      // kv heads
constexpr int D   = 128;    // head dim
constexpr int E   = 64;     // experts
constexpr int TK  = 8;      // top_k
constexpr int IM  = 768;    // moe intermediate
constexpr float EPS = 1e-6f;
constexpr int NA = S * TK;  // total assignments = 8192

// GEMM tiling
constexpr int KC  = 16;     // K-chunk
constexpr int AST = 20;     // A smem stride (floats)
constexpr int BST = 72;     // B smem stride (floats)
constexpr int MAXT = 200;   // worklist capacity (worst case 127)

// ---------------- scratch (device globals; no allocation allowed) ----------
__device__ float g_xnorm [S * H];
__device__ float g_q     [S * NH * D];
__device__ float g_k     [S * NKV * D];
__device__ float g_v     [S * NKV * D];
__device__ float g_ctx   [S * NH * D];
__device__ float g_hid2  [S * H];
__device__ float g_hnorm [S * H];
__device__ int   g_topk_id[NA];
__device__ float g_topk_w [NA];
__device__ int   g_cnt   [E];
__device__ int   g_off   [E + 1];
__device__ int   g_cur   [E];
__device__ int   g_tok   [NA];     // expert-grouped token index
__device__ float g_ew    [NA];     // expert-grouped combine weight
__device__ int   g_pos   [NA];     // assignment a -> expert-grouped row
__device__ int   g_ntile;          // number of MoE m-tiles
__device__ int   g_te    [MAXT];   // tile -> expert
__device__ int   g_tt    [MAXT];   // tile -> t0 (row offset within expert)
__device__ float g_gate  [NA * IM];        // raw gate GEMM output (grouped rows)
__device__ float g_up    [NA * IM];        // raw up GEMM output
__device__ float g_act   [NA * IM];        // weighted SwiGLU activations
__device__ float g_part  [(size_t)NA * H]; // grouped down-proj rows

__device__ __forceinline__ float* bufptr(int b) {
    switch (b) {
        case 0: return g_xnorm;
        case 4: return g_ctx;
        case 5: return g_hid2;
        case 6: return g_hnorm;
    }
    return nullptr;
}

// ---------------- helpers ----------------
__device__ __forceinline__ unsigned smaddr(const void* p) {
    return (unsigned)__cvta_generic_to_shared(p);
}
__device__ __forceinline__ unsigned cvt_tf32(float f) {
    unsigned u; asm("cvt.rna.tf32.f32 %0, %1;" : "=r"(u) : "f"(f)); return u;
}
__device__ __forceinline__ void cpa16(unsigned s, const void* g) {
    asm volatile("cp.async.ca.shared.global [%0], [%1], 16;" :: "r"(s), "l"(g));
}
__device__ __forceinline__ void cp_commit() { asm volatile("cp.async.commit_group;"); }
__device__ __forceinline__ void cp_wait0()  { asm volatile("cp.async.wait_group 0;"); }
__device__ __forceinline__ void cp_wait1()  { asm volatile("cp.async.wait_group 1;"); }
__device__ __forceinline__ void cp_wait2()  { asm volatile("cp.async.wait_group 2;"); }
__device__ __forceinline__ void mma_tf32(float c[4], const unsigned a[4], const unsigned b[2]) {
    asm volatile(
        "mma.sync.aligned.m16n8k8.row.col.f32.tf32.tf32.f32 "
        "{%0,%1,%2,%3}, {%4,%5,%6,%7}, {%8,%9}, {%0,%1,%2,%3};\n"
        : "+f"(c[0]), "+f"(c[1]), "+f"(c[2]), "+f"(c[3])
        : "r"(a[0]), "r"(a[1]), "r"(a[2]), "r"(a[3]), "r"(b[0]), "r"(b[1]));
}

// ---------------- RMSNorm ----------------
__global__ void rmsnorm_k(const float* __restrict__ x_ext, int xBuf,
                          const float* __restrict__ g, int outBuf) {
    const float* x = x_ext ? x_ext : bufptr(xBuf);
    float* out = bufptr(outBuf);
    int row = blockIdx.x, tid = threadIdx.x;
    const float* xr = x + (size_t)row * H;
    float ss = 0.f;
    for (int j = tid; j < H; j += 256) { float v = xr[j]; ss += v * v; }
    for (int o = 16; o; o >>= 1) ss += __shfl_xor_sync(0xffffffffu, ss, o);
    __shared__ float red[8];
    if ((tid & 31) == 0) red[tid >> 5] = ss;
    __syncthreads();
    if (tid < 32) {
        float v = (tid < 8) ? red[tid] : 0.f;
        for (int o = 4; o; o >>= 1) v += __shfl_xor_sync(0xffffffffu, v, o);
        if (tid == 0) red[0] = v;
    }
    __syncthreads();
    float inv = rsqrtf(red[0] / (float)H + EPS);
    for (int j = tid; j < H; j += 256) out[(size_t)row * H + j] = xr[j] * inv * g[j];
}

// ---------------- dense TF32 GEMM, cp.async double-buffered ----------------
// CTA tile 128x64, 8 warps (4m x 2n). mode 0: fused QKV (N=3072), mode 1: Wo.
__global__ __launch_bounds__(256) void dense_tf32(int aBuf,
        const float* __restrict__ W0, const float* __restrict__ W1,
        const float* __restrict__ W2, const float* __restrict__ res,
        int mode, int K) {
    const float* A = bufptr(aBuf);
    int m0 = blockIdx.y * 128;
    int n0c = blockIdx.x * 64;
    const float* B; int ldb, nb; float* Cp; int ldo;
    if (mode == 0) {
        if (n0c < 2048)      { B = W0; ldb = 2048; nb = n0c;        Cp = g_q; ldo = 2048; }
        else if (n0c < 2560) { B = W1; ldb = 512;  nb = n0c - 2048; Cp = g_k; ldo = 512; }
        else                 { B = W2; ldb = 512;  nb = n0c - 2560; Cp = g_v; ldo = 512; }
    } else { B = W0; ldb = 2048; nb = n0c; Cp = g_hid2; ldo = 2048; }
    __shared__ __align__(16) float As[2][128 * AST];
    __shared__ __align__(16) float Bs[2][KC * BST];
    int tid = threadIdx.x, lane = tid & 31, wid = tid >> 5;
    int wm = wid >> 1, wn = wid & 1;

    auto load_chunk = [&](int k0, int buf) {
        #pragma unroll
        for (int i = 0; i < 2; i++) {
            int id = tid + i * 256;
            int row = id >> 2, q = (id & 3) * 4;
            cpa16(smaddr(&As[buf][row * AST + q]),
                  A + (size_t)(m0 + row) * K + k0 + q);
        }
        int kr = tid >> 4, nq = (tid & 15) * 4;
        cpa16(smaddr(&Bs[buf][kr * BST + nq]),
              B + (size_t)(k0 + kr) * ldb + nb + nq);
        cp_commit();
    };

    float acc[2][4][4] = {};
    int NCH = K / KC;
    load_chunk(0, 0);
    for (int c = 0; c < NCH; c++) {
        int buf = c & 1;
        if (c + 1 < NCH) { load_chunk((c + 1) * KC, buf ^ 1); cp_wait1(); }
        else             { cp_wait0(); }
        __syncthreads();
        #pragma unroll
        for (int ks = 0; ks < 2; ks++) {
            int kk = ks * 8;
            unsigned Af[2][4];
            #pragma unroll
            for (int m = 0; m < 2; m++) {
                const float* ap = &As[buf][(wm * 32 + m * 16 + (lane >> 2)) * AST + kk + (lane & 3)];
                Af[m][0] = cvt_tf32(ap[0]);
                Af[m][1] = cvt_tf32(ap[8 * AST]);
                Af[m][2] = cvt_tf32(ap[4]);
                Af[m][3] = cvt_tf32(ap[8 * AST + 4]);
            }
            #pragma unroll
            for (int nt = 0; nt < 4; nt++) {
                const float* bp = &Bs[buf][(kk + (lane & 3)) * BST + wn * 32 + nt * 8 + (lane >> 2)];
                unsigned Bf[2] = { cvt_tf32(bp[0]), cvt_tf32(bp[4 * BST]) };
                #pragma unroll
                for (int m = 0; m < 2; m++) mma_tf32(acc[m][nt], Af[m], Bf);
            }
        }
        __syncthreads();
    }
    #pragma unroll
    for (int m = 0; m < 2; m++)
        #pragma unroll
        for (int nt = 0; nt < 4; nt++)
            #pragma unroll
            for (int r = 0; r < 4; r++) {
                int row = m0 + wm * 32 + m * 16 + (lane >> 2) + ((r >= 2) ? 8 : 0);
                int col = wn * 32 + nt * 8 + (lane & 3) * 2 + (r & 1);
                size_t oidx = (size_t)row * ldo + nb + col;
                float v = acc[m][nt][r];
                if (res) v += res[oidx];
                Cp[oidx] = v;
            }
}

// ---------------- causal flash attention (fp32) ----------------
__global__ __launch_bounds__(256) void attn_k() {
    constexpr int KT = 32;
    constexpr float SC = 0.0883883476483184f; // 1/sqrt(128)
    int qt = blockIdx.x, h = blockIdx.y;
    int kvh = h / (NH / NKV);
    int tid = threadIdx.x;
    int qi = tid >> 2, qr = tid & 3;
    int qrow = qt * 64 + qi;
    int d0 = qr * 32;
    __shared__ float Ks[KT][D];
    __shared__ float Vs[KT][D];
    float qreg[32], acc[32];
    #pragma unroll
    for (int d = 0; d < 32; d++) {
        qreg[d] = g_q[(size_t)qrow * (NH * D) + h * D + d0 + d] * SC;
        acc[d] = 0.f;
    }
    float m = -1e30f, l = 0.f;
    int ktiles = qt * 2 + 2;
    for (int kt = 0; kt < ktiles; kt++) {
        int kb = kt * KT;
        for (int idx = tid; idx < KT * D; idx += 256) {
            int r = idx >> 7, c = idx & 127;
            Ks[r][c] = g_k[(size_t)(kb + r) * (NKV * D) + kvh * D + c];
            Vs[r][c] = g_v[(size_t)(kb + r) * (NKV * D) + kvh * D + c];
        }
        __syncthreads();
        float sc[KT];
        #pragma unroll
        for (int j = 0; j < KT; j++) {
            float p = 0.f;
            #pragma unroll
            for (int d = 0; d < 32; d++) p += qreg[d] * Ks[j][d0 + d];
            p += __shfl_xor_sync(0xffffffffu, p, 1);
            p += __shfl_xor_sync(0xffffffffu, p, 2);
            sc[j] = (kb + j <= qrow) ? p : -1e30f;
        }
        float tm = m;
        #pragma unroll
        for (int j = 0; j < KT; j++) tm = fmaxf(tm, sc[j]);
        float corr = __expf(m - tm);
        m = tm;
        l *= corr;
        #pragma unroll
        for (int d = 0; d < 32; d++) acc[d] *= corr;
        #pragma unroll
        for (int j = 0; j < KT; j++) {
            float p = __expf(sc[j] - m);
            l += p;
            #pragma unroll
            for (int d = 0; d < 32; d++) acc[d] += p * Vs[j][d0 + d];
        }
        __syncthreads();
    }
    float inv = 1.f / l;
    #pragma unroll
    for (int d = 0; d < 32; d++)
        g_ctx[(size_t)qrow * (NH * D) + h * D + d0 + d] = acc[d] * inv;
}

// ---------------- router: logits, softmax-top8, counts ----------------
__global__ void zero_cnt_k() { if (threadIdx.x < E) g_cnt[threadIdx.x] = 0; }

__global__ void router_k(const float* __restrict__ Wg) {
    int t = blockIdx.x, tid = threadIdx.x;   // blockDim = 64
    __shared__ float sh[H];
    __shared__ float lg[E];
    for (int j = tid; j < H; j += 64) sh[j] = g_hnorm[(size_t)t * H + j];
    __syncthreads();
    float lo = 0.f;
    for (int j = 0; j < H; j++) lo += sh[j] * Wg[(size_t)j * E + tid];
    lg[tid] = lo;
    __syncthreads();
    if (tid == 0) {
        float tmp[E];
        for (int e = 0; e < E; e++) tmp[e] = lg[e];
        int   id[TK]; float w[TK];
        for (int k = 0; k < TK; k++) {
            int best = 0; float bv = tmp[0];
            for (int e = 1; e < E; e++) if (tmp[e] > bv) { bv = tmp[e]; best = e; }
            id[k] = best; w[k] = bv; tmp[best] = -1e30f;
        }
        float mx = w[0], s = 0.f;
        for (int k = 0; k < TK; k++) { w[k] = expf(w[k] - mx); s += w[k]; }
        float inv = 1.f / s;
        for (int k = 0; k < TK; k++) {
            g_topk_id[t * TK + k] = id[k];
            g_topk_w [t * TK + k] = w[k] * inv;
            atomicAdd(&g_cnt[id[k]], 1);
        }
    }
}

// offsets + compact worklist of 128-row m-tiles
__global__ void offsets_k() {
    if (threadIdx.x == 0) {
        int run = 0;
        for (int e = 0; e < E; e++) { g_off[e] = run; g_cur[e] = run; run += g_cnt[e]; }
        g_off[E] = run;
        int nt = 0;
        for (int e = 0; e < E; e++) {
            int cnt = g_off[e + 1] - g_off[e];
            for (int t0 = 0; t0 < cnt; t0 += 128) {
                g_te[nt] = e; g_tt[nt] = t0; nt++;
            }
        }
        g_ntile = nt;
    }
}

__global__ void scatter_k() {
    int a = blockIdx.x * blockDim.x + threadIdx.x;
    if (a < NA) {
        int e = g_topk_id[a];
        int pos = atomicAdd(&g_cur[e], 1);
        g_tok[pos] = a >> 3;
        g_ew [pos] = g_topk_w[a];
        g_pos[a]   = pos;
    }
}

// ---------------- MoE gate/up GEMM: worklist tiles, 3-stage pipeline -------
// grid (24, 128): x<12 -> gate n-tile x; x>=12 -> up n-tile x-12. y = tile id.
// CTA tile 128 x 64, KC=16, 3 stages (2 chunks in flight), <=45KB static smem.
__global__ __launch_bounds__(256) void moe_gu_tf32(const float* __restrict__ Wgate,
                                                   const float* __restrict__ Wup) {
    int ti = blockIdx.y;
    if (ti >= g_ntile) return;
    int e = g_te[ti], t0 = g_tt[ti];
    int base = g_off[e], cnt = g_off[e + 1] - base;
    int xx = blockIdx.x;
    const float* W; float* O;
    if (xx < 12) { W = Wgate + (size_t)e * H * IM; O = g_gate; }
    else         { W = Wup   + (size_t)e * H * IM; O = g_up; xx -= 12; }
    int i0 = xx * 64;
    __shared__ __align__(16) float As[3][128 * AST];
    __shared__ __align__(16) float Bs[3][KC * BST];
    __shared__ int stok[128];
    int tid = threadIdx.x, lane = tid & 31, wid = tid >> 5;
    int wm = wid >> 1, wn = wid & 1;
    if (tid < 128) {
        int r = t0 + tid;
        stok[tid] = (r < cnt) ? g_tok[base + r] : g_tok[base];
    }
    __syncthreads();

    auto load_chunk = [&](int k0, int buf) {
        #pragma unroll
        for (int i = 0; i < 2; i++) {
            int id = tid + i * 256;
            int row = id >> 2, q = (id & 3) * 4;
            cpa16(smaddr(&As[buf][row * AST + q]),
                  g_hnorm + (size_t)stok[row] * H + k0 + q);
        }
        int kr = tid >> 4, nq = (tid & 15) * 4;
        cpa16(smaddr(&Bs[buf][kr * BST + nq]),
              W + (size_t)(k0 + kr) * IM + i0 + nq);
        cp_commit();
    };

    float acc[2][4][4] = {};
    constexpr int NCH = H / KC;   // 128
    load_chunk(0, 0);
    load_chunk(KC, 1);
    for (int c = 0; c < NCH; c++) {
        int buf = c % 3;
        if (c + 2 < NCH) { load_chunk((c + 2) * KC, (c + 2) % 3); cp_wait2(); }
        else if (c + 1 < NCH) cp_wait1();
        else                  cp_wait0();
        __syncthreads();
        #pragma unroll
        for (int ks = 0; ks < 2; ks++) {
            int kk = ks * 8;
            unsigned Af[2][4];
            #pragma unroll
            for (int m = 0; m < 2; m++) {
                const float* ap = &As[buf][(wm * 32 + m * 16 + (lane >> 2)) * AST + kk + (lane & 3)];
                Af[m][0] = cvt_tf32(ap[0]);
                Af[m][1] = cvt_tf32(ap[8 * AST]);
                Af[m][2] = cvt_tf32(ap[4]);
                Af[m][3] = cvt_tf32(ap[8 * AST + 4]);
            }
            #pragma unroll
            for (int nt = 0; nt < 4; nt++) {
                const float* bp = &Bs[buf][(kk + (lane & 3)) * BST + wn * 32 + nt * 8 + (lane >> 2)];
                unsigned Bf[2] = { cvt_tf32(bp[0]), cvt_tf32(bp[4 * BST]) };
                #pragma unroll
                for (int m = 0; m < 2; m++) mma_tf32(acc[m][nt], Af[m], Bf);
            }
        }
        __syncthreads();
    }
    #pragma unroll
    for (int m = 0; m < 2; m++)
        #pragma unroll
        for (int nt = 0; nt < 4; nt++) {
            int rr = wm * 32 + m * 16 + (lane >> 2);
            int colb = wn * 32 + nt * 8 + (lane & 3) * 2;
            if (t0 + rr < cnt)
                *(float2*)&O[(size_t)(base + t0 + rr) * IM + i0 + colb] =
                    make_float2(acc[m][nt][0], acc[m][nt][1]);
            if (t0 + rr + 8 < cnt)
                *(float2*)&O[(size_t)(base + t0 + rr + 8) * IM + i0 + colb] =
                    make_float2(acc[m][nt][2], acc[m][nt][3]);
        }
}

// ---------------- SwiGLU + combine-weight elementwise ----------------------
__global__ void swiglu_k() {
    int i4 = blockIdx.x * 256 + threadIdx.x;       // NA*IM/4 float4s
    int p = i4 / (IM / 4);
    float w = g_ew[p];
    float4 gg = ((const float4*)g_gate)[i4];
    float4 uu = ((const float4*)g_up)[i4];
    float4 r;
    r.x = (gg.x / (1.f + __expf(-gg.x))) * uu.x * w;
    r.y = (gg.y / (1.f + __expf(-gg.y))) * uu.y * w;
    r.z = (gg.z / (1.f + __expf(-gg.z))) * uu.z * w;
    r.w = (gg.w / (1.f + __expf(-gg.w))) * uu.w * w;
    ((float4*)g_act)[i4] = r;
}

// ---------------- MoE down GEMM: worklist tiles, 3-stage pipeline ----------
// grid (32, 128). CTA tile 128 x 64, KC=16, 3 stages.
__global__ __launch_bounds__(256) void moe_down_tf32(const float* __restrict__ Wdown) {
    int ti = blockIdx.y;
    if (ti >= g_ntile) return;
    int e = g_te[ti], t0 = g_tt[ti];
    int base = g_off[e], cnt = g_off[e + 1] - base;
    int h0 = blockIdx.x * 64;
    __shared__ __align__(16) float As[3][128 * AST];
    __shared__ __align__(16) float Bs[3][KC * BST];
    int tid = threadIdx.x, lane = tid & 31, wid = tid >> 5;
    int wm = wid >> 1, wn = wid & 1;
    const float* WdE = Wdown + (size_t)e * IM * H;

    auto load_chunk = [&](int k0, int buf) {
        #pragma unroll
        for (int i = 0; i < 2; i++) {
            int id = tid + i * 256;
            int row = id >> 2, q = (id & 3) * 4;
            int gr = t0 + row; if (gr >= cnt) gr = cnt - 1;
            cpa16(smaddr(&As[buf][row * AST + q]),
                  g_act + (size_t)(base + gr) * IM + k0 + q);
        }
        int kr = tid >> 4, nq = (tid & 15) * 4;
        cpa16(smaddr(&Bs[buf][kr * BST + nq]),
              WdE + (size_t)(k0 + kr) * H + h0 + nq);
        cp_commit();
    };

    float acc[2][4][4] = {};
    constexpr int NCH = IM / KC;   // 48
    load_chunk(0, 0);
    load_chunk(KC, 1);
    for (int c = 0; c < NCH; c++) {
        int buf = c % 3;
        if (c + 2 < NCH) { load_chunk((c + 2) * KC, (c + 2) % 3); cp_wait2(); }
        else if (c + 1 < NCH) cp_wait1();
        else                  cp_wait0();
        __syncthreads();
        #pragma unroll
        for (int ks = 0; ks < 2; ks++) {
            int kk = ks * 8;
            unsigned Af[2][4];
            #pragma unroll
            for (int m = 0; m < 2; m++) {
                const float* ap = &As[buf][(wm * 32 + m * 16 + (lane >> 2)) * AST + kk + (lane & 3)];
                Af[m][0] = cvt_tf32(ap[0]);
                Af[m][1] = cvt_tf32(ap[8 * AST]);
                Af[m][2] = cvt_tf32(ap[4]);
                Af[m][3] = cvt_tf32(ap[8 * AST + 4]);
            }
            #pragma unroll
            for (int nt = 0; nt < 4; nt++) {
                const float* bp = &Bs[buf][(kk + (lane & 3)) * BST + wn * 32 + nt * 8 + (lane >> 2)];
                unsigned Bf[2] = { cvt_tf32(bp[0]), cvt_tf32(bp[4 * BST]) };
                #pragma unroll
                for (int m = 0; m < 2; m++) mma_tf32(acc[m][nt], Af[m], Bf);
            }
        }
        __syncthreads();
    }
    #pragma unroll
    for (int m = 0; m < 2; m++)
        #pragma unroll
        for (int nt = 0; nt < 4; nt++) {
            int rr = wm * 32 + m * 16 + (lane >> 2);
            int colb = wn * 32 + nt * 8 + (lane & 3) * 2;
            if (t0 + rr < cnt)
                *(float2*)&g_part[(size_t)(base + t0 + rr) * H + h0 + colb] =
                    make_float2(acc[m][nt][0], acc[m][nt][1]);
            if (t0 + rr + 8 < cnt)
                *(float2*)&g_part[(size_t)(base + t0 + rr + 8) * H + h0 + colb] =
                    make_float2(acc[m][nt][2], acc[m][nt][3]);
        }
}

// ---------------- finalize: residual + sum of 8 grouped partial rows -------
__global__ void finalize_k(float* __restrict__ out) {
    size_t idx = (size_t)blockIdx.x * 256 + threadIdx.x;   // S*H total
    int t = (int)(idx >> 11);
    int hc = (int)(idx & 2047);
    float v = g_hid2[idx];
    #pragma unroll
    for (int k = 0; k < TK; k++)
        v += g_part[(size_t)g_pos[t * TK + k] * H + hc];
    out[idx] = v;
}

// ---------------- launch ----------------
extern "C" void kernel_launch(void* const* d_in, const int* in_sizes, int n_in,
                              void* d_out, int out_size) {
    const float* hidden = (const float*)d_in[0];
    const float* ln1_g  = (const float*)d_in[1];
    const float* ln2_g  = (const float*)d_in[2];
    const float* Wq     = (const float*)d_in[3];
    const float* Wk     = (const float*)d_in[4];
    const float* Wv     = (const float*)d_in[5];
    const float* Wo     = (const float*)d_in[6];
    const float* Wg     = (const float*)d_in[7];
    const float* Wgate  = (const float*)d_in[8];
    const float* Wup    = (const float*)d_in[9];
    const float* Wdown  = (const float*)d_in[10];
    float* out = (float*)d_out;

    // 1. input RMSNorm -> buf0 (xnorm)
    rmsnorm_k<<<S, 256>>>(hidden, -1, ln1_g, 0);
    // 2. fused QKV projection
    dense_tf32<<<dim3(48, S / 128), 256>>>(0, Wq, Wk, Wv, nullptr, 0, H);
    // 3. causal GQA attention -> ctx(4)
    attn_k<<<dim3(S / 64, NH), 256>>>();
    // 4. output projection + residual -> hid2(5)
    dense_tf32<<<dim3(32, S / 128), 256>>>(4, Wo, nullptr, nullptr, hidden, 1, NH * D);
    // 5. post-attn RMSNorm -> hnorm(6)
    rmsnorm_k<<<S, 256>>>(nullptr, 5, ln2_g, 6);
    // 6. router + dispatch (+ worklist build)
    zero_cnt_k<<<1, 64>>>();
    router_k<<<S, 64>>>(Wg);
    offsets_k<<<1, 1>>>();
    scatter_k<<<(NA + 255) / 256, 256>>>();
    // 7. expert gate + up GEMMs (worklist, 3-stage pipeline)
    moe_gu_tf32<<<dim3(24, 128), 256>>>(Wgate, Wup);
    // 8. SwiGLU + combine weight
    swiglu_k<<<NA * IM / 4 / 256, 256>>>();
    // 9. expert down-proj (worklist, 3-stage pipeline)
    moe_down_tf32<<<dim3(32, 128), 256>>>(Wdown);
    // 10. residual + combine
    finalize_k<<<(S * H) / 256, 256>>>(out);
    (void)in_sizes; (void)n_in; (void)out_size;
}

// round 13
// speedup vs baseline: 1.0363x; 1.0363x over previous
#include <cuda_runtime.h>
#include <cuda_fp16.h>
#include <math.h>

// Problem constants
constexpr int S   = 1024;   // tokens
constexpr int H   = 2048;   // hidden
constexpr int NH  = 16;     // q heads
constexpr int NKV = 4;      // kv heads
constexpr int D   = 128;    // head dim
constexpr int E   = 64;     // experts
constexpr int TK  = 8;      // top_k
constexpr int IM  = 768;    // moe intermediate
constexpr float EPS = 1e-6f;
constexpr int NA = S * TK;  // total assignments = 8192

// dense GEMM tiling
constexpr int KC  = 16;     // dense K-chunk
constexpr int AST = 20;     // dense A smem stride (floats)
constexpr int BST = 72;     // dense B smem stride (floats)
// MoE fp16 tiling
constexpr int MKC  = 32;    // MoE K-chunk (halves)
constexpr int HST  = 40;    // MoE smem stride (halves), conflict-free
constexpr int MAXT = 200;   // worklist capacity

// ---------------- scratch (device globals; no allocation allowed) ----------
__device__ float g_xnorm [S * H];
__device__ float g_q     [S * NH * D];
__device__ float g_k     [S * NKV * D];
__device__ float g_v     [S * NKV * D];
__device__ float g_ctx   [S * NH * D];
__device__ float g_hid2  [S * H];
__device__ float g_hnorm [S * H];
__device__ __half g_hnorm16[S * H];
__device__ int   g_topk_id[NA];
__device__ float g_topk_w [NA];
__device__ int   g_cnt   [E];
__device__ int   g_off   [E + 1];
__device__ int   g_cur   [E];
__device__ int   g_tok   [NA];
__device__ float g_ew    [NA];
__device__ int   g_pos   [NA];
__device__ int   g_ntile;
__device__ int   g_te    [MAXT];
__device__ int   g_tt    [MAXT];
__device__ __half g_gate16[NA * IM];
__device__ __half g_up16  [NA * IM];
__device__ __half g_act16 [NA * IM];
__device__ float  g_part  [(size_t)NA * H];
// fp16 transposed weights: gate/up -> [e][IM][H], down -> [e][H][IM]
__device__ __half g_wtG[(size_t)E * IM * H];
__device__ __half g_wtU[(size_t)E * IM * H];
__device__ __half g_wdt[(size_t)E * H * IM];

__device__ __forceinline__ float* bufptr(int b) {
    switch (b) {
        case 0: return g_xnorm;
        case 4: return g_ctx;
        case 5: return g_hid2;
        case 6: return g_hnorm;
    }
    return nullptr;
}

// ---------------- helpers ----------------
__device__ __forceinline__ unsigned smaddr(const void* p) {
    return (unsigned)__cvta_generic_to_shared(p);
}
__device__ __forceinline__ unsigned cvt_tf32(float f) {
    unsigned u; asm("cvt.rna.tf32.f32 %0, %1;" : "=r"(u) : "f"(f)); return u;
}
__device__ __forceinline__ void cpa16(unsigned s, const void* g) {
    asm volatile("cp.async.ca.shared.global [%0], [%1], 16;" :: "r"(s), "l"(g));
}
__device__ __forceinline__ void cp_commit() { asm volatile("cp.async.commit_group;"); }
__device__ __forceinline__ void cp_wait0()  { asm volatile("cp.async.wait_group 0;"); }
__device__ __forceinline__ void cp_wait1()  { asm volatile("cp.async.wait_group 1;"); }
__device__ __forceinline__ void cp_wait2()  { asm volatile("cp.async.wait_group 2;"); }
__device__ __forceinline__ void mma_tf32(float c[4], const unsigned a[4], const unsigned b[2]) {
    asm volatile(
        "mma.sync.aligned.m16n8k8.row.col.f32.tf32.tf32.f32 "
        "{%0,%1,%2,%3}, {%4,%5,%6,%7}, {%8,%9}, {%0,%1,%2,%3};\n"
        : "+f"(c[0]), "+f"(c[1]), "+f"(c[2]), "+f"(c[3])
        : "r"(a[0]), "r"(a[1]), "r"(a[2]), "r"(a[3]), "r"(b[0]), "r"(b[1]));
}
__device__ __forceinline__ void mma_f16(float c[4], const unsigned a[4], const unsigned b[2]) {
    asm volatile(
        "mma.sync.aligned.m16n8k16.row.col.f32.f16.f16.f32 "
        "{%0,%1,%2,%3}, {%4,%5,%6,%7}, {%8,%9}, {%0,%1,%2,%3};\n"
        : "+f"(c[0]), "+f"(c[1]), "+f"(c[2]), "+f"(c[3])
        : "r"(a[0]), "r"(a[1]), "r"(a[2]), "r"(a[3]), "r"(b[0]), "r"(b[1]));
}

// ---------------- RMSNorm ----------------
__global__ void rmsnorm_k(const float* __restrict__ x_ext, int xBuf,
                          const float* __restrict__ g, int outBuf) {
    const float* x = x_ext ? x_ext : bufptr(xBuf);
    float* out = bufptr(outBuf);
    int row = blockIdx.x, tid = threadIdx.x;
    const float* xr = x + (size_t)row * H;
    float ss = 0.f;
    for (int j = tid; j < H; j += 256) { float v = xr[j]; ss += v * v; }
    for (int o = 16; o; o >>= 1) ss += __shfl_xor_sync(0xffffffffu, ss, o);
    __shared__ float red[8];
    if ((tid & 31) == 0) red[tid >> 5] = ss;
    __syncthreads();
    if (tid < 32) {
        float v = (tid < 8) ? red[tid] : 0.f;
        for (int o = 4; o; o >>= 1) v += __shfl_xor_sync(0xffffffffu, v, o);
        if (tid == 0) red[0] = v;
    }
    __syncthreads();
    float inv = rsqrtf(red[0] / (float)H + EPS);
    for (int j = tid; j < H; j += 256) out[(size_t)row * H + j] = xr[j] * inv * g[j];
}

// hnorm -> fp16 copy
__global__ void h2half_k() {
    int i = blockIdx.x * 256 + threadIdx.x;   // S*H/2 half2s
    float2 v = ((const float2*)g_hnorm)[i];
    ((__half2*)g_hnorm16)[i] = __floats2half2_rn(v.x, v.y);
}

// ---------------- weight transpose + fp32->fp16 convert --------------------
// in: [R][C] fp32 per expert (blockIdx.z); out: [C][R] fp16.
__global__ void wconvT_k(const float* __restrict__ W, __half* __restrict__ Wt,
                         int R, int C) {
    __shared__ float t[32][33];
    const float* We = W + (size_t)blockIdx.z * R * C;
    __half* Wte = Wt + (size_t)blockIdx.z * R * C;
    int c0 = blockIdx.x * 32, r0 = blockIdx.y * 32;
    int tx = threadIdx.x, ty = threadIdx.y;   // 32 x 8
    #pragma unroll
    for (int i = 0; i < 4; i++)
        t[ty + i * 8][tx] = We[(size_t)(r0 + ty + i * 8) * C + c0 + tx];
    __syncthreads();
    #pragma unroll
    for (int i = 0; i < 4; i++)
        Wte[(size_t)(c0 + ty + i * 8) * R + r0 + tx] = __float2half(t[tx][ty + i * 8]);
}

// ---------------- dense TF32 GEMM, cp.async double-buffered ----------------
__global__ __launch_bounds__(256) void dense_tf32(int aBuf,
        const float* __restrict__ W0, const float* __restrict__ W1,
        const float* __restrict__ W2, const float* __restrict__ res,
        int mode, int K) {
    const float* A = bufptr(aBuf);
    int m0 = blockIdx.y * 128;
    int n0c = blockIdx.x * 64;
    const float* B; int ldb, nb; float* Cp; int ldo;
    if (mode == 0) {
        if (n0c < 2048)      { B = W0; ldb = 2048; nb = n0c;        Cp = g_q; ldo = 2048; }
        else if (n0c < 2560) { B = W1; ldb = 512;  nb = n0c - 2048; Cp = g_k; ldo = 512; }
        else                 { B = W2; ldb = 512;  nb = n0c - 2560; Cp = g_v; ldo = 512; }
    } else { B = W0; ldb = 2048; nb = n0c; Cp = g_hid2; ldo = 2048; }
    __shared__ __align__(16) float As[2][128 * AST];
    __shared__ __align__(16) float Bs[2][KC * BST];
    int tid = threadIdx.x, lane = tid & 31, wid = tid >> 5;
    int wm = wid >> 1, wn = wid & 1;

    auto load_chunk = [&](int k0, int buf) {
        #pragma unroll
        for (int i = 0; i < 2; i++) {
            int id = tid + i * 256;
            int row = id >> 2, q = (id & 3) * 4;
            cpa16(smaddr(&As[buf][row * AST + q]),
                  A + (size_t)(m0 + row) * K + k0 + q);
        }
        int kr = tid >> 4, nq = (tid & 15) * 4;
        cpa16(smaddr(&Bs[buf][kr * BST + nq]),
              B + (size_t)(k0 + kr) * ldb + nb + nq);
        cp_commit();
    };

    float acc[2][4][4] = {};
    int NCH = K / KC;
    load_chunk(0, 0);
    for (int c = 0; c < NCH; c++) {
        int buf = c & 1;
        if (c + 1 < NCH) { load_chunk((c + 1) * KC, buf ^ 1); cp_wait1(); }
        else             { cp_wait0(); }
        __syncthreads();
        #pragma unroll
        for (int ks = 0; ks < 2; ks++) {
            int kk = ks * 8;
            unsigned Af[2][4];
            #pragma unroll
            for (int m = 0; m < 2; m++) {
                const float* ap = &As[buf][(wm * 32 + m * 16 + (lane >> 2)) * AST + kk + (lane & 3)];
                Af[m][0] = cvt_tf32(ap[0]);
                Af[m][1] = cvt_tf32(ap[8 * AST]);
                Af[m][2] = cvt_tf32(ap[4]);
                Af[m][3] = cvt_tf32(ap[8 * AST + 4]);
            }
            #pragma unroll
            for (int nt = 0; nt < 4; nt++) {
                const float* bp = &Bs[buf][(kk + (lane & 3)) * BST + wn * 32 + nt * 8 + (lane >> 2)];
                unsigned Bf[2] = { cvt_tf32(bp[0]), cvt_tf32(bp[4 * BST]) };
                #pragma unroll
                for (int m = 0; m < 2; m++) mma_tf32(acc[m][nt], Af[m], Bf);
            }
        }
        __syncthreads();
    }
    #pragma unroll
    for (int m = 0; m < 2; m++)
        #pragma unroll
        for (int nt = 0; nt < 4; nt++)
            #pragma unroll
            for (int r = 0; r < 4; r++) {
                int row = m0 + wm * 32 + m * 16 + (lane >> 2) + ((r >= 2) ? 8 : 0);
                int col = wn * 32 + nt * 8 + (lane & 3) * 2 + (r & 1);
                size_t oidx = (size_t)row * ldo + nb + col;
                float v = acc[m][nt][r];
                if (res) v += res[oidx];
                Cp[oidx] = v;
            }
}

// ---------------- causal flash attention (fp32) ----------------
__global__ __launch_bounds__(256) void attn_k() {
    constexpr int KT = 32;
    constexpr float SC = 0.0883883476483184f;
    int qt = blockIdx.x, h = blockIdx.y;
    int kvh = h / (NH / NKV);
    int tid = threadIdx.x;
    int qi = tid >> 2, qr = tid & 3;
    int qrow = qt * 64 + qi;
    int d0 = qr * 32;
    __shared__ float Ks[KT][D];
    __shared__ float Vs[KT][D];
    float qreg[32], acc[32];
    #pragma unroll
    for (int d = 0; d < 32; d++) {
        qreg[d] = g_q[(size_t)qrow * (NH * D) + h * D + d0 + d] * SC;
        acc[d] = 0.f;
    }
    float m = -1e30f, l = 0.f;
    int ktiles = qt * 2 + 2;
    for (int kt = 0; kt < ktiles; kt++) {
        int kb = kt * KT;
        for (int idx = tid; idx < KT * D; idx += 256) {
            int r = idx >> 7, c = idx & 127;
            Ks[r][c] = g_k[(size_t)(kb + r) * (NKV * D) + kvh * D + c];
            Vs[r][c] = g_v[(size_t)(kb + r) * (NKV * D) + kvh * D + c];
        }
        __syncthreads();
        float sc[KT];
        #pragma unroll
        for (int j = 0; j < KT; j++) {
            float p = 0.f;
            #pragma unroll
            for (int d = 0; d < 32; d++) p += qreg[d] * Ks[j][d0 + d];
            p += __shfl_xor_sync(0xffffffffu, p, 1);
            p += __shfl_xor_sync(0xffffffffu, p, 2);
            sc[j] = (kb + j <= qrow) ? p : -1e30f;
        }
        float tm = m;
        #pragma unroll
        for (int j = 0; j < KT; j++) tm = fmaxf(tm, sc[j]);
        float corr = __expf(m - tm);
        m = tm;
        l *= corr;
        #pragma unroll
        for (int d = 0; d < 32; d++) acc[d] *= corr;
        #pragma unroll
        for (int j = 0; j < KT; j++) {
            float p = __expf(sc[j] - m);
            l += p;
            #pragma unroll
            for (int d = 0; d < 32; d++) acc[d] += p * Vs[j][d0 + d];
        }
        __syncthreads();
    }
    float inv = 1.f / l;
    #pragma unroll
    for (int d = 0; d < 32; d++)
        g_ctx[(size_t)qrow * (NH * D) + h * D + d0 + d] = acc[d] * inv;
}

// ---------------- router ----------------
__global__ void zero_cnt_k() { if (threadIdx.x < E) g_cnt[threadIdx.x] = 0; }

__global__ void router_k(const float* __restrict__ Wg) {
    int t = blockIdx.x, tid = threadIdx.x;   // blockDim = 64
    __shared__ float sh[H];
    __shared__ float lg[E];
    for (int j = tid; j < H; j += 64) sh[j] = g_hnorm[(size_t)t * H + j];
    __syncthreads();
    float lo = 0.f;
    for (int j = 0; j < H; j++) lo += sh[j] * Wg[(size_t)j * E + tid];
    lg[tid] = lo;
    __syncthreads();
    if (tid == 0) {
        float tmp[E];
        for (int e = 0; e < E; e++) tmp[e] = lg[e];
        int   id[TK]; float w[TK];
        for (int k = 0; k < TK; k++) {
            int best = 0; float bv = tmp[0];
            for (int e = 1; e < E; e++) if (tmp[e] > bv) { bv = tmp[e]; best = e; }
            id[k] = best; w[k] = bv; tmp[best] = -1e30f;
        }
        float mx = w[0], s = 0.f;
        for (int k = 0; k < TK; k++) { w[k] = expf(w[k] - mx); s += w[k]; }
        float inv = 1.f / s;
        for (int k = 0; k < TK; k++) {
            g_topk_id[t * TK + k] = id[k];
            g_topk_w [t * TK + k] = w[k] * inv;
            atomicAdd(&g_cnt[id[k]], 1);
        }
    }
}

__global__ void offsets_k() {
    if (threadIdx.x == 0) {
        int run = 0;
        for (int e = 0; e < E; e++) { g_off[e] = run; g_cur[e] = run; run += g_cnt[e]; }
        g_off[E] = run;
        int nt = 0;
        for (int e = 0; e < E; e++) {
            int cnt = g_off[e + 1] - g_off[e];
            for (int t0 = 0; t0 < cnt; t0 += 128) {
                g_te[nt] = e; g_tt[nt] = t0; nt++;
            }
        }
        g_ntile = nt;
    }
}

__global__ void scatter_k() {
    int a = blockIdx.x * blockDim.x + threadIdx.x;
    if (a < NA) {
        int e = g_topk_id[a];
        int pos = atomicAdd(&g_cur[e], 1);
        g_tok[pos] = a >> 3;
        g_ew [pos] = g_topk_w[a];
        g_pos[a]   = pos;
    }
}

// ---------------- MoE gate/up fp16 GEMM: transposed weights, 3-stage -------
// grid (24, 128): x<12 -> gate, else up. y = worklist tile. CTA 128 x 64, KC=32.
__global__ __launch_bounds__(256) void moe_gu_f16() {
    int ti = blockIdx.y;
    if (ti >= g_ntile) return;
    int e = g_te[ti], t0 = g_tt[ti];
    int base = g_off[e], cnt = g_off[e + 1] - base;
    int xx = blockIdx.x;
    const __half* Wt; __half* O;
    if (xx < 12) { Wt = g_wtG + (size_t)e * IM * H; O = g_gate16; }
    else         { Wt = g_wtU + (size_t)e * IM * H; O = g_up16; xx -= 12; }
    int i0 = xx * 64;
    __shared__ __align__(16) __half As[3][128 * HST];
    __shared__ __align__(16) __half Bs[3][64 * HST];
    __shared__ int stok[128];
    int tid = threadIdx.x, lane = tid & 31, wid = tid >> 5;
    int wm = wid >> 1, wn = wid & 1;
    if (tid < 128) {
        int r = t0 + tid;
        stok[tid] = (r < cnt) ? g_tok[base + r] : g_tok[base];
    }
    __syncthreads();

    auto load_chunk = [&](int k0, int buf) {
        #pragma unroll
        for (int i = 0; i < 2; i++) {
            int id = tid + i * 256;
            int row = id >> 2, q = (id & 3) * 8;
            cpa16(smaddr(&As[buf][row * HST + q]),
                  g_hnorm16 + (size_t)stok[row] * H + k0 + q);
        }
        int nr = tid >> 2, q = (tid & 3) * 8;
        cpa16(smaddr(&Bs[buf][nr * HST + q]),
              Wt + (size_t)(i0 + nr) * H + k0 + q);
        cp_commit();
    };

    float acc[2][4][4] = {};
    constexpr int NCH = H / MKC;   // 64
    load_chunk(0, 0);
    load_chunk(MKC, 1);
    for (int c = 0; c < NCH; c++) {
        int buf = c % 3;
        if (c + 2 < NCH) { load_chunk((c + 2) * MKC, (c + 2) % 3); cp_wait2(); }
        else if (c + 1 < NCH) cp_wait1();
        else                  cp_wait0();
        __syncthreads();
        #pragma unroll
        for (int ks = 0; ks < 2; ks++) {
            int kk = ks * 16;
            unsigned Af[2][4];
            #pragma unroll
            for (int m = 0; m < 2; m++) {
                const __half* ap = &As[buf][(wm * 32 + m * 16 + (lane >> 2)) * HST + kk + (lane & 3) * 2];
                Af[m][0] = *(const unsigned*)(ap);
                Af[m][1] = *(const unsigned*)(ap + 8 * HST);
                Af[m][2] = *(const unsigned*)(ap + 8);
                Af[m][3] = *(const unsigned*)(ap + 8 * HST + 8);
            }
            #pragma unroll
            for (int ng = 0; ng < 4; ng++) {
                const __half* bp = &Bs[buf][(wn * 32 + ng * 8 + (lane >> 2)) * HST + kk + (lane & 3) * 2];
                unsigned Bf[2] = { *(const unsigned*)(bp), *(const unsigned*)(bp + 8) };
                #pragma unroll
                for (int m = 0; m < 2; m++) mma_f16(acc[m][ng], Af[m], Bf);
            }
        }
        __syncthreads();
    }
    #pragma unroll
    for (int m = 0; m < 2; m++)
        #pragma unroll
        for (int ng = 0; ng < 4; ng++) {
            int rr = wm * 32 + m * 16 + (lane >> 2);
            int colb = wn * 32 + ng * 8 + (lane & 3) * 2;
            if (t0 + rr < cnt)
                *(__half2*)&O[(size_t)(base + t0 + rr) * IM + i0 + colb] =
                    __floats2half2_rn(acc[m][ng][0], acc[m][ng][1]);
            if (t0 + rr + 8 < cnt)
                *(__half2*)&O[(size_t)(base + t0 + rr + 8) * IM + i0 + colb] =
                    __floats2half2_rn(acc[m][ng][2], acc[m][ng][3]);
        }
}

// ---------------- SwiGLU + combine-weight (fp16 in/out) --------------------
__global__ void swiglu_k() {
    int i2 = blockIdx.x * 256 + threadIdx.x;   // NA*IM/2 half2s
    int p = i2 / (IM / 2);
    float w = g_ew[p];
    __half2 g2 = ((const __half2*)g_gate16)[i2];
    __half2 u2 = ((const __half2*)g_up16)[i2];
    float gx = __low2float(g2), gy = __high2float(g2);
    float ux = __low2float(u2), uy = __high2float(u2);
    float ax = (gx / (1.f + __expf(-gx))) * ux * w;
    float ay = (gy / (1.f + __expf(-gy))) * uy * w;
    ((__half2*)g_act16)[i2] = __floats2half2_rn(ax, ay);
}

// ---------------- MoE down fp16 GEMM -> grouped fp32 partial rows ----------
// grid (32, 128). CTA 128 x 64, KC=32, K=IM.
__global__ __launch_bounds__(256) void moe_down_f16() {
    int ti = blockIdx.y;
    if (ti >= g_ntile) return;
    int e = g_te[ti], t0 = g_tt[ti];
    int base = g_off[e], cnt = g_off[e + 1] - base;
    int h0 = blockIdx.x * 64;
    __shared__ __align__(16) __half As[3][128 * HST];
    __shared__ __align__(16) __half Bs[3][64 * HST];
    int tid = threadIdx.x, lane = tid & 31, wid = tid >> 5;
    int wm = wid >> 1, wn = wid & 1;
    const __half* Wt = g_wdt + (size_t)e * H * IM;

    auto load_chunk = [&](int k0, int buf) {
        #pragma unroll
        for (int i = 0; i < 2; i++) {
            int id = tid + i * 256;
            int row = id >> 2, q = (id & 3) * 8;
            int gr = t0 + row; if (gr >= cnt) gr = cnt - 1;
            cpa16(smaddr(&As[buf][row * HST + q]),
                  g_act16 + (size_t)(base + gr) * IM + k0 + q);
        }
        int nr = tid >> 2, q = (tid & 3) * 8;
        cpa16(smaddr(&Bs[buf][nr * HST + q]),
              Wt + (size_t)(h0 + nr) * IM + k0 + q);
        cp_commit();
    };

    float acc[2][4][4] = {};
    constexpr int NCH = IM / MKC;   // 24
    load_chunk(0, 0);
    load_chunk(MKC, 1);
    for (int c = 0; c < NCH; c++) {
        int buf = c % 3;
        if (c + 2 < NCH) { load_chunk((c + 2) * MKC, (c + 2) % 3); cp_wait2(); }
        else if (c + 1 < NCH) cp_wait1();
        else                  cp_wait0();
        __syncthreads();
        #pragma unroll
        for (int ks = 0; ks < 2; ks++) {
            int kk = ks * 16;
            unsigned Af[2][4];
            #pragma unroll
            for (int m = 0; m < 2; m++) {
                const __half* ap = &As[buf][(wm * 32 + m * 16 + (lane >> 2)) * HST + kk + (lane & 3) * 2];
                Af[m][0] = *(const unsigned*)(ap);
                Af[m][1] = *(const unsigned*)(ap + 8 * HST);
                Af[m][2] = *(const unsigned*)(ap + 8);
                Af[m][3] = *(const unsigned*)(ap + 8 * HST + 8);
            }
            #pragma unroll
            for (int ng = 0; ng < 4; ng++) {
                const __half* bp = &Bs[buf][(wn * 32 + ng * 8 + (lane >> 2)) * HST + kk + (lane & 3) * 2];
                unsigned Bf[2] = { *(const unsigned*)(bp), *(const unsigned*)(bp + 8) };
                #pragma unroll
                for (int m = 0; m < 2; m++) mma_f16(acc[m][ng], Af[m], Bf);
            }
        }
        __syncthreads();
    }
    #pragma unroll
    for (int m = 0; m < 2; m++)
        #pragma unroll
        for (int ng = 0; ng < 4; ng++) {
            int rr = wm * 32 + m * 16 + (lane >> 2);
            int colb = wn * 32 + ng * 8 + (lane & 3) * 2;
            if (t0 + rr < cnt)
                *(float2*)&g_part[(size_t)(base + t0 + rr) * H + h0 + colb] =
                    make_float2(acc[m][ng][0], acc[m][ng][1]);
            if (t0 + rr + 8 < cnt)
                *(float2*)&g_part[(size_t)(base + t0 + rr + 8) * H + h0 + colb] =
                    make_float2(acc[m][ng][2], acc[m][ng][3]);
        }
}

// ---------------- finalize ----------------
__global__ void finalize_k(float* __restrict__ out) {
    size_t idx = (size_t)blockIdx.x * 256 + threadIdx.x;
    int t = (int)(idx >> 11);
    int hc = (int)(idx & 2047);
    float v = g_hid2[idx];
    #pragma unroll
    for (int k = 0; k < TK; k++)
        v += g_part[(size_t)g_pos[t * TK + k] * H + hc];
    out[idx] = v;
}

// ---------------- launch ----------------
extern "C" void kernel_launch(void* const* d_in, const int* in_sizes, int n_in,
                              void* d_out, int out_size) {
    const float* hidden = (const float*)d_in[0];
    const float* ln1_g  = (const float*)d_in[1];
    const float* ln2_g  = (const float*)d_in[2];
    const float* Wq     = (const float*)d_in[3];
    const float* Wk     = (const float*)d_in[4];
    const float* Wv     = (const float*)d_in[5];
    const float* Wo     = (const float*)d_in[6];
    const float* Wg     = (const float*)d_in[7];
    const float* Wgate  = (const float*)d_in[8];
    const float* Wup    = (const float*)d_in[9];
    const float* Wdown  = (const float*)d_in[10];
    float* out = (float*)d_out;

    __half *p_wtG = nullptr, *p_wtU = nullptr, *p_wdt = nullptr;
    cudaGetSymbolAddress((void**)&p_wtG, g_wtG);
    cudaGetSymbolAddress((void**)&p_wtU, g_wtU);
    cudaGetSymbolAddress((void**)&p_wdt, g_wdt);

    // 0. weight transpose+convert (independent of the rest; launch first)
    wconvT_k<<<dim3(IM / 32, H / 32, E), dim3(32, 8)>>>(Wgate, p_wtG, H, IM);
    wconvT_k<<<dim3(IM / 32, H / 32, E), dim3(32, 8)>>>(Wup,   p_wtU, H, IM);
    wconvT_k<<<dim3(H / 32, IM / 32, E), dim3(32, 8)>>>(Wdown, p_wdt, IM, H);

    // 1. input RMSNorm -> buf0 (xnorm)
    rmsnorm_k<<<S, 256>>>(hidden, -1, ln1_g, 0);
    // 2. fused QKV projection
    dense_tf32<<<dim3(48, S / 128), 256>>>(0, Wq, Wk, Wv, nullptr, 0, H);
    // 3. causal GQA attention -> ctx(4)
    attn_k<<<dim3(S / 64, NH), 256>>>();
    // 4. output projection + residual -> hid2(5)
    dense_tf32<<<dim3(32, S / 128), 256>>>(4, Wo, nullptr, nullptr, hidden, 1, NH * D);
    // 5. post-attn RMSNorm -> hnorm(6), + fp16 copy
    rmsnorm_k<<<S, 256>>>(nullptr, 5, ln2_g, 6);
    h2half_k<<<S * H / 2 / 256, 256>>>();
    // 6. router + dispatch + worklist
    zero_cnt_k<<<1, 64>>>();
    router_k<<<S, 64>>>(Wg);
    offsets_k<<<1, 1>>>();
    scatter_k<<<(NA + 255) / 256, 256>>>();
    // 7. expert gate + up GEMMs (fp16, transposed weights)
    moe_gu_f16<<<dim3(24, 128), 256>>>();
    // 8. SwiGLU + combine weight
    swiglu_k<<<NA * IM / 2 / 256, 256>>>();
    // 9. expert down-proj (fp16)
    moe_down_f16<<<dim3(32, 128), 256>>>();
    // 10. residual + combine
    finalize_k<<<(S * H) / 256, 256>>>(out);
    (void)in_sizes; (void)n_in; (void)out_size;
}

// round 14
// speedup vs baseline: 1.0974x; 1.0590x over previous
#include <cuda_runtime.h>
#include <cuda_fp16.h>
#include <math.h>

// Problem constants
constexpr int S   = 1024;   // tokens
constexpr int H   = 2048;   // hidden
constexpr int NH  = 16;     // q heads
constexpr int NKV = 4;      // kv heads
constexpr int D   = 128;    // head dim
constexpr int E   = 64;     // experts
constexpr int TK  = 8;      // top_k
constexpr int IM  = 768;    // moe intermediate
constexpr float EPS = 1e-6f;
constexpr int NA = S * TK;  // total assignments = 8192

// dense GEMM tiling
constexpr int KC  = 16;     // dense K-chunk
constexpr int AST = 20;     // dense A smem stride (floats)
constexpr int BST = 72;     // dense B smem stride (floats)
// MoE fp16 tiling
constexpr int MKC = 32;     // MoE K-chunk (halves)
constexpr int HST = 40;     // A smem stride (halves), conflict-free
constexpr int BSH = 72;     // B smem stride (halves), conflict-free
constexpr int MAXT = 200;   // worklist capacity

// ---------------- scratch (device globals; no allocation allowed) ----------
__device__ float g_xnorm [S * H];
__device__ float g_q     [S * NH * D];
__device__ float g_k     [S * NKV * D];
__device__ float g_v     [S * NKV * D];
__device__ float g_ctx   [S * NH * D];
__device__ float g_hid2  [S * H];
__device__ float g_hnorm [S * H];
__device__ __half g_hnorm16[S * H];
__device__ int   g_topk_id[NA];
__device__ float g_topk_w [NA];
__device__ int   g_cnt   [E];
__device__ int   g_off   [E + 1];
__device__ int   g_cur   [E];
__device__ int   g_tok   [NA];
__device__ float g_ew    [NA];
__device__ int   g_pos   [NA];
__device__ int   g_ntile;
__device__ int   g_te    [MAXT];
__device__ int   g_tt    [MAXT];
__device__ __half g_gate16[NA * IM];
__device__ __half g_up16  [NA * IM];
__device__ __half g_act16 [NA * IM];
__device__ float  g_part  [(size_t)NA * H];
// fp16 weights, SAME layout as inputs (K-major): gate/up [e][H][IM], down [e][IM][H]
__device__ __half g_w16G[(size_t)E * H * IM];
__device__ __half g_w16U[(size_t)E * H * IM];
__device__ __half g_w16D[(size_t)E * IM * H];

__device__ __forceinline__ float* bufptr(int b) {
    switch (b) {
        case 0: return g_xnorm;
        case 4: return g_ctx;
        case 5: return g_hid2;
        case 6: return g_hnorm;
    }
    return nullptr;
}

// ---------------- helpers ----------------
__device__ __forceinline__ unsigned smaddr(const void* p) {
    return (unsigned)__cvta_generic_to_shared(p);
}
__device__ __forceinline__ unsigned cvt_tf32(float f) {
    unsigned u; asm("cvt.rna.tf32.f32 %0, %1;" : "=r"(u) : "f"(f)); return u;
}
__device__ __forceinline__ void cpa16(unsigned s, const void* g) {
    asm volatile("cp.async.ca.shared.global [%0], [%1], 16;" :: "r"(s), "l"(g));
}
__device__ __forceinline__ void cp_commit() { asm volatile("cp.async.commit_group;"); }
__device__ __forceinline__ void cp_wait0()  { asm volatile("cp.async.wait_group 0;"); }
__device__ __forceinline__ void cp_wait1()  { asm volatile("cp.async.wait_group 1;"); }
__device__ __forceinline__ void cp_wait2()  { asm volatile("cp.async.wait_group 2;"); }
__device__ __forceinline__ void ldsm_x4(unsigned r[4], unsigned a) {
    asm volatile("ldmatrix.sync.aligned.m8n8.x4.shared.b16 {%0,%1,%2,%3}, [%4];"
        : "=r"(r[0]), "=r"(r[1]), "=r"(r[2]), "=r"(r[3]) : "r"(a));
}
__device__ __forceinline__ void ldsm_x4_t(unsigned r[4], unsigned a) {
    asm volatile("ldmatrix.sync.aligned.m8n8.x4.trans.shared.b16 {%0,%1,%2,%3}, [%4];"
        : "=r"(r[0]), "=r"(r[1]), "=r"(r[2]), "=r"(r[3]) : "r"(a));
}
__device__ __forceinline__ void mma_tf32(float c[4], const unsigned a[4], const unsigned b[2]) {
    asm volatile(
        "mma.sync.aligned.m16n8k8.row.col.f32.tf32.tf32.f32 "
        "{%0,%1,%2,%3}, {%4,%5,%6,%7}, {%8,%9}, {%0,%1,%2,%3};\n"
        : "+f"(c[0]), "+f"(c[1]), "+f"(c[2]), "+f"(c[3])
        : "r"(a[0]), "r"(a[1]), "r"(a[2]), "r"(a[3]), "r"(b[0]), "r"(b[1]));
}
__device__ __forceinline__ void mma_f16(float c[4], const unsigned a[4], const unsigned b[2]) {
    asm volatile(
        "mma.sync.aligned.m16n8k16.row.col.f32.f16.f16.f32 "
        "{%0,%1,%2,%3}, {%4,%5,%6,%7}, {%8,%9}, {%0,%1,%2,%3};\n"
        : "+f"(c[0]), "+f"(c[1]), "+f"(c[2]), "+f"(c[3])
        : "r"(a[0]), "r"(a[1]), "r"(a[2]), "r"(a[3]), "r"(b[0]), "r"(b[1]));
}

// ---------------- RMSNorm ----------------
__global__ void rmsnorm_k(const float* __restrict__ x_ext, int xBuf,
                          const float* __restrict__ g, int outBuf) {
    const float* x = x_ext ? x_ext : bufptr(xBuf);
    float* out = bufptr(outBuf);
    int row = blockIdx.x, tid = threadIdx.x;
    const float* xr = x + (size_t)row * H;
    float ss = 0.f;
    for (int j = tid; j < H; j += 256) { float v = xr[j]; ss += v * v; }
    for (int o = 16; o; o >>= 1) ss += __shfl_xor_sync(0xffffffffu, ss, o);
    __shared__ float red[8];
    if ((tid & 31) == 0) red[tid >> 5] = ss;
    __syncthreads();
    if (tid < 32) {
        float v = (tid < 8) ? red[tid] : 0.f;
        for (int o = 4; o; o >>= 1) v += __shfl_xor_sync(0xffffffffu, v, o);
        if (tid == 0) red[0] = v;
    }
    __syncthreads();
    float inv = rsqrtf(red[0] / (float)H + EPS);
    for (int j = tid; j < H; j += 256) out[(size_t)row * H + j] = xr[j] * inv * g[j];
}

// hnorm -> fp16 copy
__global__ void h2half_k() {
    int i = blockIdx.x * 256 + threadIdx.x;   // S*H/2 half2s
    float2 v = ((const float2*)g_hnorm)[i];
    ((__half2*)g_hnorm16)[i] = __floats2half2_rn(v.x, v.y);
}

// ---------------- weight fp32 -> fp16 convert (same layout, coalesced) -----
// dst: 0 = g_w16G, 1 = g_w16U, 2 = g_w16D. 8 elems/thread, 16B read+read/16B write.
__global__ void wconv_k(const float* __restrict__ W, int dstSel) {
    __half* dst = (dstSel == 0) ? g_w16G : (dstSel == 1) ? g_w16U : g_w16D;
    size_t i8 = (size_t)blockIdx.x * 256 + threadIdx.x;   // index of 8-elem group
    const float4* src = (const float4*)W + i8 * 2;
    float4 a = src[0], b = src[1];
    __half2 h0 = __floats2half2_rn(a.x, a.y);
    __half2 h1 = __floats2half2_rn(a.z, a.w);
    __half2 h2 = __floats2half2_rn(b.x, b.y);
    __half2 h3 = __floats2half2_rn(b.z, b.w);
    uint4 o;
    o.x = *(unsigned*)&h0; o.y = *(unsigned*)&h1;
    o.z = *(unsigned*)&h2; o.w = *(unsigned*)&h3;
    ((uint4*)dst)[i8] = o;
}

// ---------------- dense TF32 GEMM, cp.async double-buffered ----------------
__global__ __launch_bounds__(256) void dense_tf32(int aBuf,
        const float* __restrict__ W0, const float* __restrict__ W1,
        const float* __restrict__ W2, const float* __restrict__ res,
        int mode, int K) {
    const float* A = bufptr(aBuf);
    int m0 = blockIdx.y * 128;
    int n0c = blockIdx.x * 64;
    const float* B; int ldb, nb; float* Cp; int ldo;
    if (mode == 0) {
        if (n0c < 2048)      { B = W0; ldb = 2048; nb = n0c;        Cp = g_q; ldo = 2048; }
        else if (n0c < 2560) { B = W1; ldb = 512;  nb = n0c - 2048; Cp = g_k; ldo = 512; }
        else                 { B = W2; ldb = 512;  nb = n0c - 2560; Cp = g_v; ldo = 512; }
    } else { B = W0; ldb = 2048; nb = n0c; Cp = g_hid2; ldo = 2048; }
    __shared__ __align__(16) float As[2][128 * AST];
    __shared__ __align__(16) float Bs[2][KC * BST];
    int tid = threadIdx.x, lane = tid & 31, wid = tid >> 5;
    int wm = wid >> 1, wn = wid & 1;

    auto load_chunk = [&](int k0, int buf) {
        #pragma unroll
        for (int i = 0; i < 2; i++) {
            int id = tid + i * 256;
            int row = id >> 2, q = (id & 3) * 4;
            cpa16(smaddr(&As[buf][row * AST + q]),
                  A + (size_t)(m0 + row) * K + k0 + q);
        }
        int kr = tid >> 4, nq = (tid & 15) * 4;
        cpa16(smaddr(&Bs[buf][kr * BST + nq]),
              B + (size_t)(k0 + kr) * ldb + nb + nq);
        cp_commit();
    };

    float acc[2][4][4] = {};
    int NCH = K / KC;
    load_chunk(0, 0);
    for (int c = 0; c < NCH; c++) {
        int buf = c & 1;
        if (c + 1 < NCH) { load_chunk((c + 1) * KC, buf ^ 1); cp_wait1(); }
        else             { cp_wait0(); }
        __syncthreads();
        #pragma unroll
        for (int ks = 0; ks < 2; ks++) {
            int kk = ks * 8;
            unsigned Af[2][4];
            #pragma unroll
            for (int m = 0; m < 2; m++) {
                const float* ap = &As[buf][(wm * 32 + m * 16 + (lane >> 2)) * AST + kk + (lane & 3)];
                Af[m][0] = cvt_tf32(ap[0]);
                Af[m][1] = cvt_tf32(ap[8 * AST]);
                Af[m][2] = cvt_tf32(ap[4]);
                Af[m][3] = cvt_tf32(ap[8 * AST + 4]);
            }
            #pragma unroll
            for (int nt = 0; nt < 4; nt++) {
                const float* bp = &Bs[buf][(kk + (lane & 3)) * BST + wn * 32 + nt * 8 + (lane >> 2)];
                unsigned Bf[2] = { cvt_tf32(bp[0]), cvt_tf32(bp[4 * BST]) };
                #pragma unroll
                for (int m = 0; m < 2; m++) mma_tf32(acc[m][nt], Af[m], Bf);
            }
        }
        __syncthreads();
    }
    #pragma unroll
    for (int m = 0; m < 2; m++)
        #pragma unroll
        for (int nt = 0; nt < 4; nt++)
            #pragma unroll
            for (int r = 0; r < 4; r++) {
                int row = m0 + wm * 32 + m * 16 + (lane >> 2) + ((r >= 2) ? 8 : 0);
                int col = wn * 32 + nt * 8 + (lane & 3) * 2 + (r & 1);
                size_t oidx = (size_t)row * ldo + nb + col;
                float v = acc[m][nt][r];
                if (res) v += res[oidx];
                Cp[oidx] = v;
            }
}

// ---------------- causal flash attention (fp32) ----------------
__global__ __launch_bounds__(256) void attn_k() {
    constexpr int KT = 32;
    constexpr float SC = 0.0883883476483184f;
    int qt = blockIdx.x, h = blockIdx.y;
    int kvh = h / (NH / NKV);
    int tid = threadIdx.x;
    int qi = tid >> 2, qr = tid & 3;
    int qrow = qt * 64 + qi;
    int d0 = qr * 32;
    __shared__ float Ks[KT][D];
    __shared__ float Vs[KT][D];
    float qreg[32], acc[32];
    #pragma unroll
    for (int d = 0; d < 32; d++) {
        qreg[d] = g_q[(size_t)qrow * (NH * D) + h * D + d0 + d] * SC;
        acc[d] = 0.f;
    }
    float m = -1e30f, l = 0.f;
    int ktiles = qt * 2 + 2;
    for (int kt = 0; kt < ktiles; kt++) {
        int kb = kt * KT;
        for (int idx = tid; idx < KT * D; idx += 256) {
            int r = idx >> 7, c = idx & 127;
            Ks[r][c] = g_k[(size_t)(kb + r) * (NKV * D) + kvh * D + c];
            Vs[r][c] = g_v[(size_t)(kb + r) * (NKV * D) + kvh * D + c];
        }
        __syncthreads();
        float sc[KT];
        #pragma unroll
        for (int j = 0; j < KT; j++) {
            float p = 0.f;
            #pragma unroll
            for (int d = 0; d < 32; d++) p += qreg[d] * Ks[j][d0 + d];
            p += __shfl_xor_sync(0xffffffffu, p, 1);
            p += __shfl_xor_sync(0xffffffffu, p, 2);
            sc[j] = (kb + j <= qrow) ? p : -1e30f;
        }
        float tm = m;
        #pragma unroll
        for (int j = 0; j < KT; j++) tm = fmaxf(tm, sc[j]);
        float corr = __expf(m - tm);
        m = tm;
        l *= corr;
        #pragma unroll
        for (int d = 0; d < 32; d++) acc[d] *= corr;
        #pragma unroll
        for (int j = 0; j < KT; j++) {
            float p = __expf(sc[j] - m);
            l += p;
            #pragma unroll
            for (int d = 0; d < 32; d++) acc[d] += p * Vs[j][d0 + d];
        }
        __syncthreads();
    }
    float inv = 1.f / l;
    #pragma unroll
    for (int d = 0; d < 32; d++)
        g_ctx[(size_t)qrow * (NH * D) + h * D + d0 + d] = acc[d] * inv;
}

// ---------------- router ----------------
__global__ void zero_cnt_k() { if (threadIdx.x < E) g_cnt[threadIdx.x] = 0; }

__global__ void router_k(const float* __restrict__ Wg) {
    int t = blockIdx.x, tid = threadIdx.x;   // blockDim = 64
    __shared__ float sh[H];
    __shared__ float lg[E];
    for (int j = tid; j < H; j += 64) sh[j] = g_hnorm[(size_t)t * H + j];
    __syncthreads();
    float lo = 0.f;
    for (int j = 0; j < H; j++) lo += sh[j] * Wg[(size_t)j * E + tid];
    lg[tid] = lo;
    __syncthreads();
    if (tid == 0) {
        float tmp[E];
        for (int e = 0; e < E; e++) tmp[e] = lg[e];
        int   id[TK]; float w[TK];
        for (int k = 0; k < TK; k++) {
            int best = 0; float bv = tmp[0];
            for (int e = 1; e < E; e++) if (tmp[e] > bv) { bv = tmp[e]; best = e; }
            id[k] = best; w[k] = bv; tmp[best] = -1e30f;
        }
        float mx = w[0], s = 0.f;
        for (int k = 0; k < TK; k++) { w[k] = expf(w[k] - mx); s += w[k]; }
        float inv = 1.f / s;
        for (int k = 0; k < TK; k++) {
            g_topk_id[t * TK + k] = id[k];
            g_topk_w [t * TK + k] = w[k] * inv;
            atomicAdd(&g_cnt[id[k]], 1);
        }
    }
}

__global__ void offsets_k() {
    if (threadIdx.x == 0) {
        int run = 0;
        for (int e = 0; e < E; e++) { g_off[e] = run; g_cur[e] = run; run += g_cnt[e]; }
        g_off[E] = run;
        int nt = 0;
        for (int e = 0; e < E; e++) {
            int cnt = g_off[e + 1] - g_off[e];
            for (int t0 = 0; t0 < cnt; t0 += 128) {
                g_te[nt] = e; g_tt[nt] = t0; nt++;
            }
        }
        g_ntile = nt;
    }
}

__global__ void scatter_k() {
    int a = blockIdx.x * blockDim.x + threadIdx.x;
    if (a < NA) {
        int e = g_topk_id[a];
        int pos = atomicAdd(&g_cur[e], 1);
        g_tok[pos] = a >> 3;
        g_ew [pos] = g_topk_w[a];
        g_pos[a]   = pos;
    }
}

// ---------------- MoE gate/up fp16 GEMM: K-major B + ldmatrix, 3-stage -----
// grid (24, 128): x<12 -> gate, else up. y = worklist tile. CTA 128 x 64, KC=32.
__global__ __launch_bounds__(256) void moe_gu_f16() {
    int ti = blockIdx.y;
    if (ti >= g_ntile) return;
    int e = g_te[ti], t0 = g_tt[ti];
    int base = g_off[e], cnt = g_off[e + 1] - base;
    int xx = blockIdx.x;
    const __half* W16; __half* O;
    if (xx < 12) { W16 = g_w16G + (size_t)e * H * IM; O = g_gate16; }
    else         { W16 = g_w16U + (size_t)e * H * IM; O = g_up16; xx -= 12; }
    int i0 = xx * 64;
    __shared__ __align__(16) __half As[3][128 * HST];   // [row][k]
    __shared__ __align__(16) __half Bs[3][MKC * BSH];   // [k][n]
    __shared__ int stok[128];
    int tid = threadIdx.x, lane = tid & 31, wid = tid >> 5;
    int wm = wid >> 1, wn = wid & 1;
    int lg = lane >> 3, lr8 = lane & 7;
    if (tid < 128) {
        int r = t0 + tid;
        stok[tid] = (r < cnt) ? g_tok[base + r] : g_tok[base];
    }
    __syncthreads();

    auto load_chunk = [&](int k0, int buf) {
        #pragma unroll
        for (int i = 0; i < 2; i++) {
            int id = tid + i * 256;
            int row = id >> 2, q = (id & 3) * 8;
            cpa16(smaddr(&As[buf][row * HST + q]),
                  g_hnorm16 + (size_t)stok[row] * H + k0 + q);
        }
        int kr = tid >> 3, q = (tid & 7) * 8;
        cpa16(smaddr(&Bs[buf][kr * BSH + q]),
              W16 + (size_t)(k0 + kr) * IM + i0 + q);
        cp_commit();
    };

    float acc[2][4][4] = {};
    constexpr int NCH = H / MKC;   // 64
    load_chunk(0, 0);
    load_chunk(MKC, 1);
    for (int c = 0; c < NCH; c++) {
        int buf = c % 3;
        if (c + 2 < NCH) { load_chunk((c + 2) * MKC, (c + 2) % 3); cp_wait2(); }
        else if (c + 1 < NCH) cp_wait1();
        else                  cp_wait0();
        __syncthreads();
        #pragma unroll
        for (int ks = 0; ks < 2; ks++) {
            int kk = ks * 16;
            unsigned Af[2][4];
            #pragma unroll
            for (int m = 0; m < 2; m++) {
                int row = wm * 32 + m * 16 + lr8 + (lg & 1) * 8;
                int col = kk + (lg >> 1) * 8;
                ldsm_x4(Af[m], smaddr(&As[buf][row * HST + col]));
            }
            #pragma unroll
            for (int np = 0; np < 2; np++) {
                int n0w = wn * 32 + np * 16;
                int brow = kk + lr8 + (lg & 1) * 8;
                int bcol = n0w + (lg >> 1) * 8;
                unsigned Bf[4];
                ldsm_x4_t(Bf, smaddr(&Bs[buf][brow * BSH + bcol]));
                #pragma unroll
                for (int m = 0; m < 2; m++) {
                    mma_f16(acc[m][np * 2 + 0], Af[m], Bf + 0);
                    mma_f16(acc[m][np * 2 + 1], Af[m], Bf + 2);
                }
            }
        }
        __syncthreads();
    }
    #pragma unroll
    for (int m = 0; m < 2; m++)
        #pragma unroll
        for (int ng = 0; ng < 4; ng++) {
            int rr = wm * 32 + m * 16 + (lane >> 2);
            int colb = wn * 32 + ng * 8 + (lane & 3) * 2;
            if (t0 + rr < cnt)
                *(__half2*)&O[(size_t)(base + t0 + rr) * IM + i0 + colb] =
                    __floats2half2_rn(acc[m][ng][0], acc[m][ng][1]);
            if (t0 + rr + 8 < cnt)
                *(__half2*)&O[(size_t)(base + t0 + rr + 8) * IM + i0 + colb] =
                    __floats2half2_rn(acc[m][ng][2], acc[m][ng][3]);
        }
}

// ---------------- SwiGLU + combine-weight (fp16 in/out) --------------------
__global__ void swiglu_k() {
    int i2 = blockIdx.x * 256 + threadIdx.x;   // NA*IM/2 half2s
    int p = i2 / (IM / 2);
    float w = g_ew[p];
    __half2 g2 = ((const __half2*)g_gate16)[i2];
    __half2 u2 = ((const __half2*)g_up16)[i2];
    float gx = __low2float(g2), gy = __high2float(g2);
    float ux = __low2float(u2), uy = __high2float(u2);
    float ax = (gx / (1.f + __expf(-gx))) * ux * w;
    float ay = (gy / (1.f + __expf(-gy))) * uy * w;
    ((__half2*)g_act16)[i2] = __floats2half2_rn(ax, ay);
}

// ---------------- MoE down fp16 GEMM -> grouped fp32 partial rows ----------
// grid (32, 128). CTA 128 x 64, KC=32, K=IM.
__global__ __launch_bounds__(256) void moe_down_f16() {
    int ti = blockIdx.y;
    if (ti >= g_ntile) return;
    int e = g_te[ti], t0 = g_tt[ti];
    int base = g_off[e], cnt = g_off[e + 1] - base;
    int h0 = blockIdx.x * 64;
    __shared__ __align__(16) __half As[3][128 * HST];
    __shared__ __align__(16) __half Bs[3][MKC * BSH];
    int tid = threadIdx.x, lane = tid & 31, wid = tid >> 5;
    int wm = wid >> 1, wn = wid & 1;
    int lg = lane >> 3, lr8 = lane & 7;
    const __half* W16 = g_w16D + (size_t)e * IM * H;

    auto load_chunk = [&](int k0, int buf) {
        #pragma unroll
        for (int i = 0; i < 2; i++) {
            int id = tid + i * 256;
            int row = id >> 2, q = (id & 3) * 8;
            int gr = t0 + row; if (gr >= cnt) gr = cnt - 1;
            cpa16(smaddr(&As[buf][row * HST + q]),
                  g_act16 + (size_t)(base + gr) * IM + k0 + q);
        }
        int kr = tid >> 3, q = (tid & 7) * 8;
        cpa16(smaddr(&Bs[buf][kr * BSH + q]),
              W16 + (size_t)(k0 + kr) * H + h0 + q);
        cp_commit();
    };

    float acc[2][4][4] = {};
    constexpr int NCH = IM / MKC;   // 24
    load_chunk(0, 0);
    load_chunk(MKC, 1);
    for (int c = 0; c < NCH; c++) {
        int buf = c % 3;
        if (c + 2 < NCH) { load_chunk((c + 2) * MKC, (c + 2) % 3); cp_wait2(); }
        else if (c + 1 < NCH) cp_wait1();
        else                  cp_wait0();
        __syncthreads();
        #pragma unroll
        for (int ks = 0; ks < 2; ks++) {
            int kk = ks * 16;
            unsigned Af[2][4];
            #pragma unroll
            for (int m = 0; m < 2; m++) {
                int row = wm * 32 + m * 16 + lr8 + (lg & 1) * 8;
                int col = kk + (lg >> 1) * 8;
                ldsm_x4(Af[m], smaddr(&As[buf][row * HST + col]));
            }
            #pragma unroll
            for (int np = 0; np < 2; np++) {
                int n0w = wn * 32 + np * 16;
                int brow = kk + lr8 + (lg & 1) * 8;
                int bcol = n0w + (lg >> 1) * 8;
                unsigned Bf[4];
                ldsm_x4_t(Bf, smaddr(&Bs[buf][brow * BSH + bcol]));
                #pragma unroll
                for (int m = 0; m < 2; m++) {
                    mma_f16(acc[m][np * 2 + 0], Af[m], Bf + 0);
                    mma_f16(acc[m][np * 2 + 1], Af[m], Bf + 2);
                }
            }
        }
        __syncthreads();
    }
    #pragma unroll
    for (int m = 0; m < 2; m++)
        #pragma unroll
        for (int ng = 0; ng < 4; ng++) {
            int rr = wm * 32 + m * 16 + (lane >> 2);
            int colb = wn * 32 + ng * 8 + (lane & 3) * 2;
            if (t0 + rr < cnt)
                *(float2*)&g_part[(size_t)(base + t0 + rr) * H + h0 + colb] =
                    make_float2(acc[m][ng][0], acc[m][ng][1]);
            if (t0 + rr + 8 < cnt)
                *(float2*)&g_part[(size_t)(base + t0 + rr + 8) * H + h0 + colb] =
                    make_float2(acc[m][ng][2], acc[m][ng][3]);
        }
}

// ---------------- finalize ----------------
__global__ void finalize_k(float* __restrict__ out) {
    size_t idx = (size_t)blockIdx.x * 256 + threadIdx.x;
    int t = (int)(idx >> 11);
    int hc = (int)(idx & 2047);
    float v = g_hid2[idx];
    #pragma unroll
    for (int k = 0; k < TK; k++)
        v += g_part[(size_t)g_pos[t * TK + k] * H + hc];
    out[idx] = v;
}

// ---------------- launch ----------------
extern "C" void kernel_launch(void* const* d_in, const int* in_sizes, int n_in,
                              void* d_out, int out_size) {
    const float* hidden = (const float*)d_in[0];
    const float* ln1_g  = (const float*)d_in[1];
    const float* ln2_g  = (const float*)d_in[2];
    const float* Wq     = (const float*)d_in[3];
    const float* Wk     = (const float*)d_in[4];
    const float* Wv     = (const float*)d_in[5];
    const float* Wo     = (const float*)d_in[6];
    const float* Wg     = (const float*)d_in[7];
    const float* Wgate  = (const float*)d_in[8];
    const float* Wup    = (const float*)d_in[9];
    const float* Wdown  = (const float*)d_in[10];
    float* out = (float*)d_out;

    // 0. weight fp32->fp16 convert (same layout; pure streaming)
    constexpr int WELEMS = E * H * IM;          // = E*IM*H
    wconv_k<<<WELEMS / 8 / 256, 256>>>(Wgate, 0);
    wconv_k<<<WELEMS / 8 / 256, 256>>>(Wup,   1);
    wconv_k<<<WELEMS / 8 / 256, 256>>>(Wdown, 2);

    // 1. input RMSNorm -> buf0 (xnorm)
    rmsnorm_k<<<S, 256>>>(hidden, -1, ln1_g, 0);
    // 2. fused QKV projection
    dense_tf32<<<dim3(48, S / 128), 256>>>(0, Wq, Wk, Wv, nullptr, 0, H);
    // 3. causal GQA attention -> ctx(4)
    attn_k<<<dim3(S / 64, NH), 256>>>();
    // 4. output projection + residual -> hid2(5)
    dense_tf32<<<dim3(32, S / 128), 256>>>(4, Wo, nullptr, nullptr, hidden, 1, NH * D);
    // 5. post-attn RMSNorm -> hnorm(6), + fp16 copy
    rmsnorm_k<<<S, 256>>>(nullptr, 5, ln2_g, 6);
    h2half_k<<<S * H / 2 / 256, 256>>>();
    // 6. router + dispatch + worklist
    zero_cnt_k<<<1, 64>>>();
    router_k<<<S, 64>>>(Wg);
    offsets_k<<<1, 1>>>();
    scatter_k<<<(NA + 255) / 256, 256>>>();
    // 7. expert gate + up GEMMs (fp16, K-major weights, ldmatrix)
    moe_gu_f16<<<dim3(24, 128), 256>>>();
    // 8. SwiGLU + combine weight
    swiglu_k<<<NA * IM / 2 / 256, 256>>>();
    // 9. expert down-proj (fp16)
    moe_down_f16<<<dim3(32, 128), 256>>>();
    // 10. residual + combine
    finalize_k<<<(S * H) / 256, 256>>>(out);
    (void)in_sizes; (void)n_in; (void)out_size;
}

// round 15
// speedup vs baseline: 1.1162x; 1.0171x over previous
#include <cuda_runtime.h>
#include <cuda_fp16.h>
#include <math.h>

// Problem constants
constexpr int S   = 1024;   // tokens
constexpr int H   = 2048;   // hidden
constexpr int NH  = 16;     // q heads
constexpr int NKV = 4;      // kv heads
constexpr int D   = 128;    // head dim
constexpr int E   = 64;     // experts
constexpr int TK  = 8;      // top_k
constexpr int IM  = 768;    // moe intermediate
constexpr float EPS = 1e-6f;
constexpr int NA = S * TK;  // total assignments = 8192

// dense GEMM tiling
constexpr int KC  = 16;     // dense K-chunk
constexpr int AST = 20;     // dense A smem stride (floats)
constexpr int BST = 72;     // dense B smem stride (floats)
// MoE fp16 tiling
constexpr int MKC = 32;     // MoE K-chunk (halves)
constexpr int HST = 40;     // A smem stride (halves), conflict-free
constexpr int BSH = 72;     // B smem stride (halves), conflict-free
constexpr int MAXT = 200;   // worklist capacity

// ---------------- scratch (device globals; no allocation allowed) ----------
__device__ float g_xnorm [S * H];
__device__ float g_q     [S * NH * D];
__device__ float g_k     [S * NKV * D];
__device__ float g_v     [S * NKV * D];
__device__ float g_ctx   [S * NH * D];
__device__ float g_hid2  [S * H];
__device__ float g_hnorm [S * H];
__device__ __half g_hnorm16[S * H];
__device__ int   g_topk_id[NA];
__device__ float g_topk_w [NA];
__device__ int   g_cnt   [E];
__device__ int   g_off   [E + 1];
__device__ int   g_cur   [E];
__device__ int   g_tok   [NA];
__device__ float g_ew    [NA];
__device__ int   g_pos   [NA];
__device__ int   g_ntile;
__device__ int   g_te    [MAXT];
__device__ int   g_tt    [MAXT];
__device__ __half g_gate16[NA * IM];
__device__ __half g_up16  [NA * IM];
__device__ __half g_act16 [NA * IM];
__device__ float  g_part  [(size_t)NA * H];
// fp16 weights, SAME layout as inputs (K-major): gate/up [e][H][IM], down [e][IM][H]
__device__ __half g_w16G[(size_t)E * H * IM];
__device__ __half g_w16U[(size_t)E * H * IM];
__device__ __half g_w16D[(size_t)E * IM * H];

__device__ __forceinline__ float* bufptr(int b) {
    switch (b) {
        case 0: return g_xnorm;
        case 4: return g_ctx;
        case 5: return g_hid2;
        case 6: return g_hnorm;
    }
    return nullptr;
}

// ---------------- helpers ----------------
__device__ __forceinline__ unsigned smaddr(const void* p) {
    return (unsigned)__cvta_generic_to_shared(p);
}
__device__ __forceinline__ unsigned cvt_tf32(float f) {
    unsigned u; asm("cvt.rna.tf32.f32 %0, %1;" : "=r"(u) : "f"(f)); return u;
}
__device__ __forceinline__ void cpa16(unsigned s, const void* g) {
    asm volatile("cp.async.ca.shared.global [%0], [%1], 16;" :: "r"(s), "l"(g));
}
__device__ __forceinline__ void cp_commit() { asm volatile("cp.async.commit_group;"); }
__device__ __forceinline__ void cp_wait0()  { asm volatile("cp.async.wait_group 0;"); }
__device__ __forceinline__ void cp_wait1()  { asm volatile("cp.async.wait_group 1;"); }
__device__ __forceinline__ void cp_wait2()  { asm volatile("cp.async.wait_group 2;"); }
__device__ __forceinline__ void ldsm_x4(unsigned r[4], unsigned a) {
    asm volatile("ldmatrix.sync.aligned.m8n8.x4.shared.b16 {%0,%1,%2,%3}, [%4];"
        : "=r"(r[0]), "=r"(r[1]), "=r"(r[2]), "=r"(r[3]) : "r"(a));
}
__device__ __forceinline__ void ldsm_x4_t(unsigned r[4], unsigned a) {
    asm volatile("ldmatrix.sync.aligned.m8n8.x4.trans.shared.b16 {%0,%1,%2,%3}, [%4];"
        : "=r"(r[0]), "=r"(r[1]), "=r"(r[2]), "=r"(r[3]) : "r"(a));
}
__device__ __forceinline__ void mma_tf32(float c[4], const unsigned a[4], const unsigned b[2]) {
    asm volatile(
        "mma.sync.aligned.m16n8k8.row.col.f32.tf32.tf32.f32 "
        "{%0,%1,%2,%3}, {%4,%5,%6,%7}, {%8,%9}, {%0,%1,%2,%3};\n"
        : "+f"(c[0]), "+f"(c[1]), "+f"(c[2]), "+f"(c[3])
        : "r"(a[0]), "r"(a[1]), "r"(a[2]), "r"(a[3]), "r"(b[0]), "r"(b[1]));
}
__device__ __forceinline__ void mma_f16(float c[4], const unsigned a[4], const unsigned b[2]) {
    asm volatile(
        "mma.sync.aligned.m16n8k16.row.col.f32.f16.f16.f32 "
        "{%0,%1,%2,%3}, {%4,%5,%6,%7}, {%8,%9}, {%0,%1,%2,%3};\n"
        : "+f"(c[0]), "+f"(c[1]), "+f"(c[2]), "+f"(c[3])
        : "r"(a[0]), "r"(a[1]), "r"(a[2]), "r"(a[3]), "r"(b[0]), "r"(b[1]));
}

// ---------------- RMSNorm (optionally also writes fp16 copy) ----------------
__global__ void rmsnorm_k(const float* __restrict__ x_ext, int xBuf,
                          const float* __restrict__ g, int outBuf, int alsoHalf) {
    const float* x = x_ext ? x_ext : bufptr(xBuf);
    float* out = bufptr(outBuf);
    int row = blockIdx.x, tid = threadIdx.x;
    const float* xr = x + (size_t)row * H;
    float ss = 0.f;
    for (int j = tid; j < H; j += 256) { float v = xr[j]; ss += v * v; }
    for (int o = 16; o; o >>= 1) ss += __shfl_xor_sync(0xffffffffu, ss, o);
    __shared__ float red[8];
    if ((tid & 31) == 0) red[tid >> 5] = ss;
    __syncthreads();
    if (tid < 32) {
        float v = (tid < 8) ? red[tid] : 0.f;
        for (int o = 4; o; o >>= 1) v += __shfl_xor_sync(0xffffffffu, v, o);
        if (tid == 0) red[0] = v;
    }
    __syncthreads();
    float inv = rsqrtf(red[0] / (float)H + EPS);
    for (int j = tid; j < H; j += 256) {
        float r = xr[j] * inv * g[j];
        out[(size_t)row * H + j] = r;
        if (alsoHalf) g_hnorm16[(size_t)row * H + j] = __float2half(r);
    }
}

// ---------------- weight fp32 -> fp16 convert (same layout, coalesced) -----
__global__ void wconv_k(const float* __restrict__ W, int dstSel) {
    __half* dst = (dstSel == 0) ? g_w16G : (dstSel == 1) ? g_w16U : g_w16D;
    size_t i8 = (size_t)blockIdx.x * 256 + threadIdx.x;   // index of 8-elem group
    const float4* src = (const float4*)W + i8 * 2;
    float4 a = src[0], b = src[1];
    __half2 h0 = __floats2half2_rn(a.x, a.y);
    __half2 h1 = __floats2half2_rn(a.z, a.w);
    __half2 h2 = __floats2half2_rn(b.x, b.y);
    __half2 h3 = __floats2half2_rn(b.z, b.w);
    uint4 o;
    o.x = *(unsigned*)&h0; o.y = *(unsigned*)&h1;
    o.z = *(unsigned*)&h2; o.w = *(unsigned*)&h3;
    ((uint4*)dst)[i8] = o;
}

// ---------------- dense TF32 GEMM, cp.async double-buffered ----------------
__global__ __launch_bounds__(256) void dense_tf32(int aBuf,
        const float* __restrict__ W0, const float* __restrict__ W1,
        const float* __restrict__ W2, const float* __restrict__ res,
        int mode, int K) {
    const float* A = bufptr(aBuf);
    int m0 = blockIdx.y * 128;
    int n0c = blockIdx.x * 64;
    const float* B; int ldb, nb; float* Cp; int ldo;
    if (mode == 0) {
        if (n0c < 2048)      { B = W0; ldb = 2048; nb = n0c;        Cp = g_q; ldo = 2048; }
        else if (n0c < 2560) { B = W1; ldb = 512;  nb = n0c - 2048; Cp = g_k; ldo = 512; }
        else                 { B = W2; ldb = 512;  nb = n0c - 2560; Cp = g_v; ldo = 512; }
    } else { B = W0; ldb = 2048; nb = n0c; Cp = g_hid2; ldo = 2048; }
    __shared__ __align__(16) float As[2][128 * AST];
    __shared__ __align__(16) float Bs[2][KC * BST];
    int tid = threadIdx.x, lane = tid & 31, wid = tid >> 5;
    int wm = wid >> 1, wn = wid & 1;

    auto load_chunk = [&](int k0, int buf) {
        #pragma unroll
        for (int i = 0; i < 2; i++) {
            int id = tid + i * 256;
            int row = id >> 2, q = (id & 3) * 4;
            cpa16(smaddr(&As[buf][row * AST + q]),
                  A + (size_t)(m0 + row) * K + k0 + q);
        }
        int kr = tid >> 4, nq = (tid & 15) * 4;
        cpa16(smaddr(&Bs[buf][kr * BST + nq]),
              B + (size_t)(k0 + kr) * ldb + nb + nq);
        cp_commit();
    };

    float acc[2][4][4] = {};
    int NCH = K / KC;
    load_chunk(0, 0);
    for (int c = 0; c < NCH; c++) {
        int buf = c & 1;
        if (c + 1 < NCH) { load_chunk((c + 1) * KC, buf ^ 1); cp_wait1(); }
        else             { cp_wait0(); }
        __syncthreads();
        #pragma unroll
        for (int ks = 0; ks < 2; ks++) {
            int kk = ks * 8;
            unsigned Af[2][4];
            #pragma unroll
            for (int m = 0; m < 2; m++) {
                const float* ap = &As[buf][(wm * 32 + m * 16 + (lane >> 2)) * AST + kk + (lane & 3)];
                Af[m][0] = cvt_tf32(ap[0]);
                Af[m][1] = cvt_tf32(ap[8 * AST]);
                Af[m][2] = cvt_tf32(ap[4]);
                Af[m][3] = cvt_tf32(ap[8 * AST + 4]);
            }
            #pragma unroll
            for (int nt = 0; nt < 4; nt++) {
                const float* bp = &Bs[buf][(kk + (lane & 3)) * BST + wn * 32 + nt * 8 + (lane >> 2)];
                unsigned Bf[2] = { cvt_tf32(bp[0]), cvt_tf32(bp[4 * BST]) };
                #pragma unroll
                for (int m = 0; m < 2; m++) mma_tf32(acc[m][nt], Af[m], Bf);
            }
        }
        __syncthreads();
    }
    #pragma unroll
    for (int m = 0; m < 2; m++)
        #pragma unroll
        for (int nt = 0; nt < 4; nt++)
            #pragma unroll
            for (int r = 0; r < 4; r++) {
                int row = m0 + wm * 32 + m * 16 + (lane >> 2) + ((r >= 2) ? 8 : 0);
                int col = wn * 32 + nt * 8 + (lane & 3) * 2 + (r & 1);
                size_t oidx = (size_t)row * ldo + nb + col;
                float v = acc[m][nt][r];
                if (res) v += res[oidx];
                Cp[oidx] = v;
            }
}

// ---------------- causal flash attention (fp32) ----------------
__global__ __launch_bounds__(256) void attn_k() {
    constexpr int KT = 32;
    constexpr float SC = 0.0883883476483184f;
    int qt = blockIdx.x, h = blockIdx.y;
    int kvh = h / (NH / NKV);
    int tid = threadIdx.x;
    int qi = tid >> 2, qr = tid & 3;
    int qrow = qt * 64 + qi;
    int d0 = qr * 32;
    __shared__ float Ks[KT][D];
    __shared__ float Vs[KT][D];
    float qreg[32], acc[32];
    #pragma unroll
    for (int d = 0; d < 32; d++) {
        qreg[d] = g_q[(size_t)qrow * (NH * D) + h * D + d0 + d] * SC;
        acc[d] = 0.f;
    }
    float m = -1e30f, l = 0.f;
    int ktiles = qt * 2 + 2;
    for (int kt = 0; kt < ktiles; kt++) {
        int kb = kt * KT;
        for (int idx = tid; idx < KT * D; idx += 256) {
            int r = idx >> 7, c = idx & 127;
            Ks[r][c] = g_k[(size_t)(kb + r) * (NKV * D) + kvh * D + c];
            Vs[r][c] = g_v[(size_t)(kb + r) * (NKV * D) + kvh * D + c];
        }
        __syncthreads();
        float sc[KT];
        #pragma unroll
        for (int j = 0; j < KT; j++) {
            float p = 0.f;
            #pragma unroll
            for (int d = 0; d < 32; d++) p += qreg[d] * Ks[j][d0 + d];
            p += __shfl_xor_sync(0xffffffffu, p, 1);
            p += __shfl_xor_sync(0xffffffffu, p, 2);
            sc[j] = (kb + j <= qrow) ? p : -1e30f;
        }
        float tm = m;
        #pragma unroll
        for (int j = 0; j < KT; j++) tm = fmaxf(tm, sc[j]);
        float corr = __expf(m - tm);
        m = tm;
        l *= corr;
        #pragma unroll
        for (int d = 0; d < 32; d++) acc[d] *= corr;
        #pragma unroll
        for (int j = 0; j < KT; j++) {
            float p = __expf(sc[j] - m);
            l += p;
            #pragma unroll
            for (int d = 0; d < 32; d++) acc[d] += p * Vs[j][d0 + d];
        }
        __syncthreads();
    }
    float inv = 1.f / l;
    #pragma unroll
    for (int d = 0; d < 32; d++)
        g_ctx[(size_t)qrow * (NH * D) + h * D + d0 + d] = acc[d] * inv;
}

// ---------------- router ----------------
__global__ void zero_cnt_k() { if (threadIdx.x < E) g_cnt[threadIdx.x] = 0; }

__global__ void router_k(const float* __restrict__ Wg) {
    int t = blockIdx.x, tid = threadIdx.x;   // blockDim = 64
    __shared__ float sh[H];
    __shared__ float lg[E];
    for (int j = tid; j < H; j += 64) sh[j] = g_hnorm[(size_t)t * H + j];
    __syncthreads();
    float lo = 0.f;
    for (int j = 0; j < H; j++) lo += sh[j] * Wg[(size_t)j * E + tid];
    lg[tid] = lo;
    __syncthreads();
    if (tid == 0) {
        float tmp[E];
        for (int e = 0; e < E; e++) tmp[e] = lg[e];
        int   id[TK]; float w[TK];
        for (int k = 0; k < TK; k++) {
            int best = 0; float bv = tmp[0];
            for (int e = 1; e < E; e++) if (tmp[e] > bv) { bv = tmp[e]; best = e; }
            id[k] = best; w[k] = bv; tmp[best] = -1e30f;
        }
        float mx = w[0], s = 0.f;
        for (int k = 0; k < TK; k++) { w[k] = expf(w[k] - mx); s += w[k]; }
        float inv = 1.f / s;
        for (int k = 0; k < TK; k++) {
            g_topk_id[t * TK + k] = id[k];
            g_topk_w [t * TK + k] = w[k] * inv;
            atomicAdd(&g_cnt[id[k]], 1);
        }
    }
}

__global__ void offsets_k() {
    if (threadIdx.x == 0) {
        int run = 0;
        for (int e = 0; e < E; e++) { g_off[e] = run; g_cur[e] = run; run += g_cnt[e]; }
        g_off[E] = run;
        int nt = 0;
        for (int e = 0; e < E; e++) {
            int cnt = g_off[e + 1] - g_off[e];
            for (int t0 = 0; t0 < cnt; t0 += 128) {
                g_te[nt] = e; g_tt[nt] = t0; nt++;
            }
        }
        g_ntile = nt;
    }
}

__global__ void scatter_k() {
    int a = blockIdx.x * blockDim.x + threadIdx.x;
    if (a < NA) {
        int e = g_topk_id[a];
        int pos = atomicAdd(&g_cur[e], 1);
        g_tok[pos] = a >> 3;
        g_ew [pos] = g_topk_w[a];
        g_pos[a]   = pos;
    }
}

// ---------------- MoE gate/up fp16 GEMM: K-major B + ldmatrix, 3-stage -----
__global__ __launch_bounds__(256) void moe_gu_f16() {
    int ti = blockIdx.y;
    if (ti >= g_ntile) return;
    int e = g_te[ti], t0 = g_tt[ti];
    int base = g_off[e], cnt = g_off[e + 1] - base;
    int xx = blockIdx.x;
    const __half* W16; __half* O;
    if (xx < 12) { W16 = g_w16G + (size_t)e * H * IM; O = g_gate16; }
    else         { W16 = g_w16U + (size_t)e * H * IM; O = g_up16; xx -= 12; }
    int i0 = xx * 64;
    __shared__ __align__(16) __half As[3][128 * HST];   // [row][k]
    __shared__ __align__(16) __half Bs[3][MKC * BSH];   // [k][n]
    __shared__ int stok[128];
    int tid = threadIdx.x, lane = tid & 31, wid = tid >> 5;
    int wm = wid >> 1, wn = wid & 1;
    int lg = lane >> 3, lr8 = lane & 7;
    if (tid < 128) {
        int r = t0 + tid;
        stok[tid] = (r < cnt) ? g_tok[base + r] : g_tok[base];
    }
    __syncthreads();

    auto load_chunk = [&](int k0, int buf) {
        #pragma unroll
        for (int i = 0; i < 2; i++) {
            int id = tid + i * 256;
            int row = id >> 2, q = (id & 3) * 8;
            cpa16(smaddr(&As[buf][row * HST + q]),
                  g_hnorm16 + (size_t)stok[row] * H + k0 + q);
        }
        int kr = tid >> 3, q = (tid & 7) * 8;
        cpa16(smaddr(&Bs[buf][kr * BSH + q]),
              W16 + (size_t)(k0 + kr) * IM + i0 + q);
        cp_commit();
    };

    float acc[2][4][4] = {};
    constexpr int NCH = H / MKC;   // 64
    load_chunk(0, 0);
    load_chunk(MKC, 1);
    for (int c = 0; c < NCH; c++) {
        int buf = c % 3;
        if (c + 2 < NCH) { load_chunk((c + 2) * MKC, (c + 2) % 3); cp_wait2(); }
        else if (c + 1 < NCH) cp_wait1();
        else                  cp_wait0();
        __syncthreads();
        #pragma unroll
        for (int ks = 0; ks < 2; ks++) {
            int kk = ks * 16;
            unsigned Af[2][4];
            #pragma unroll
            for (int m = 0; m < 2; m++) {
                int row = wm * 32 + m * 16 + lr8 + (lg & 1) * 8;
                int col = kk + (lg >> 1) * 8;
                ldsm_x4(Af[m], smaddr(&As[buf][row * HST + col]));
            }
            #pragma unroll
            for (int np = 0; np < 2; np++) {
                int n0w = wn * 32 + np * 16;
                int brow = kk + lr8 + (lg & 1) * 8;
                int bcol = n0w + (lg >> 1) * 8;
                unsigned Bf[4];
                ldsm_x4_t(Bf, smaddr(&Bs[buf][brow * BSH + bcol]));
                #pragma unroll
                for (int m = 0; m < 2; m++) {
                    mma_f16(acc[m][np * 2 + 0], Af[m], Bf + 0);
                    mma_f16(acc[m][np * 2 + 1], Af[m], Bf + 2);
                }
            }
        }
        __syncthreads();
    }
    #pragma unroll
    for (int m = 0; m < 2; m++)
        #pragma unroll
        for (int ng = 0; ng < 4; ng++) {
            int rr = wm * 32 + m * 16 + (lane >> 2);
            int colb = wn * 32 + ng * 8 + (lane & 3) * 2;
            if (t0 + rr < cnt)
                *(__half2*)&O[(size_t)(base + t0 + rr) * IM + i0 + colb] =
                    __floats2half2_rn(acc[m][ng][0], acc[m][ng][1]);
            if (t0 + rr + 8 < cnt)
                *(__half2*)&O[(size_t)(base + t0 + rr + 8) * IM + i0 + colb] =
                    __floats2half2_rn(acc[m][ng][2], acc[m][ng][3]);
        }
}

// ---------------- SwiGLU + combine-weight (fp16 in/out) --------------------
__global__ void swiglu_k() {
    int i2 = blockIdx.x * 256 + threadIdx.x;   // NA*IM/2 half2s
    int p = i2 / (IM / 2);
    float w = g_ew[p];
    __half2 g2 = ((const __half2*)g_gate16)[i2];
    __half2 u2 = ((const __half2*)g_up16)[i2];
    float gx = __low2float(g2), gy = __high2float(g2);
    float ux = __low2float(u2), uy = __high2float(u2);
    float ax = (gx / (1.f + __expf(-gx))) * ux * w;
    float ay = (gy / (1.f + __expf(-gy))) * uy * w;
    ((__half2*)g_act16)[i2] = __floats2half2_rn(ax, ay);
}

// ---------------- MoE down fp16 GEMM -> grouped fp32 partial rows ----------
__global__ __launch_bounds__(256) void moe_down_f16() {
    int ti = blockIdx.y;
    if (ti >= g_ntile) return;
    int e = g_te[ti], t0 = g_tt[ti];
    int base = g_off[e], cnt = g_off[e + 1] - base;
    int h0 = blockIdx.x * 64;
    __shared__ __align__(16) __half As[3][128 * HST];
    __shared__ __align__(16) __half Bs[3][MKC * BSH];
    int tid = threadIdx.x, lane = tid & 31, wid = tid >> 5;
    int wm = wid >> 1, wn = wid & 1;
    int lg = lane >> 3, lr8 = lane & 7;
    const __half* W16 = g_w16D + (size_t)e * IM * H;

    auto load_chunk = [&](int k0, int buf) {
        #pragma unroll
        for (int i = 0; i < 2; i++) {
            int id = tid + i * 256;
            int row = id >> 2, q = (id & 3) * 8;
            int gr = t0 + row; if (gr >= cnt) gr = cnt - 1;
            cpa16(smaddr(&As[buf][row * HST + q]),
                  g_act16 + (size_t)(base + gr) * IM + k0 + q);
        }
        int kr = tid >> 3, q = (tid & 7) * 8;
        cpa16(smaddr(&Bs[buf][kr * BSH + q]),
              W16 + (size_t)(k0 + kr) * H + h0 + q);
        cp_commit();
    };

    float acc[2][4][4] = {};
    constexpr int NCH = IM / MKC;   // 24
    load_chunk(0, 0);
    load_chunk(MKC, 1);
    for (int c = 0; c < NCH; c++) {
        int buf = c % 3;
        if (c + 2 < NCH) { load_chunk((c + 2) * MKC, (c + 2) % 3); cp_wait2(); }
        else if (c + 1 < NCH) cp_wait1();
        else                  cp_wait0();
        __syncthreads();
        #pragma unroll
        for (int ks = 0; ks < 2; ks++) {
            int kk = ks * 16;
            unsigned Af[2][4];
            #pragma unroll
            for (int m = 0; m < 2; m++) {
                int row = wm * 32 + m * 16 + lr8 + (lg & 1) * 8;
                int col = kk + (lg >> 1) * 8;
                ldsm_x4(Af[m], smaddr(&As[buf][row * HST + col]));
            }
            #pragma unroll
            for (int np = 0; np < 2; np++) {
                int n0w = wn * 32 + np * 16;
                int brow = kk + lr8 + (lg & 1) * 8;
                int bcol = n0w + (lg >> 1) * 8;
                unsigned Bf[4];
                ldsm_x4_t(Bf, smaddr(&Bs[buf][brow * BSH + bcol]));
                #pragma unroll
                for (int m = 0; m < 2; m++) {
                    mma_f16(acc[m][np * 2 + 0], Af[m], Bf + 0);
                    mma_f16(acc[m][np * 2 + 1], Af[m], Bf + 2);
                }
            }
        }
        __syncthreads();
    }
    #pragma unroll
    for (int m = 0; m < 2; m++)
        #pragma unroll
        for (int ng = 0; ng < 4; ng++) {
            int rr = wm * 32 + m * 16 + (lane >> 2);
            int colb = wn * 32 + ng * 8 + (lane & 3) * 2;
            if (t0 + rr < cnt)
                *(float2*)&g_part[(size_t)(base + t0 + rr) * H + h0 + colb] =
                    make_float2(acc[m][ng][0], acc[m][ng][1]);
            if (t0 + rr + 8 < cnt)
                *(float2*)&g_part[(size_t)(base + t0 + rr + 8) * H + h0 + colb] =
                    make_float2(acc[m][ng][2], acc[m][ng][3]);
        }
}

// ---------------- finalize ----------------
__global__ void finalize_k(float* __restrict__ out) {
    size_t idx = (size_t)blockIdx.x * 256 + threadIdx.x;
    int t = (int)(idx >> 11);
    int hc = (int)(idx & 2047);
    float v = g_hid2[idx];
    #pragma unroll
    for (int k = 0; k < TK; k++)
        v += g_part[(size_t)g_pos[t * TK + k] * H + hc];
    out[idx] = v;
}

// ---------------- launch ----------------
extern "C" void kernel_launch(void* const* d_in, const int* in_sizes, int n_in,
                              void* d_out, int out_size) {
    const float* hidden = (const float*)d_in[0];
    const float* ln1_g  = (const float*)d_in[1];
    const float* ln2_g  = (const float*)d_in[2];
    const float* Wq     = (const float*)d_in[3];
    const float* Wk     = (const float*)d_in[4];
    const float* Wv     = (const float*)d_in[5];
    const float* Wo     = (const float*)d_in[6];
    const float* Wg     = (const float*)d_in[7];
    const float* Wgate  = (const float*)d_in[8];
    const float* Wup    = (const float*)d_in[9];
    const float* Wdown  = (const float*)d_in[10];
    float* out = (float*)d_out;

    // side stream + events for overlapping weight conversion (created once,
    // on the uncaptured correctness call; reused as graph dependency nodes)
    static cudaStream_t s2 = nullptr;
    static cudaEvent_t evFork = nullptr, evJoin = nullptr;
    if (!s2) {
        cudaStreamCreateWithFlags(&s2, cudaStreamNonBlocking);
        cudaEventCreateWithFlags(&evFork, cudaEventDisableTiming);
        cudaEventCreateWithFlags(&evJoin, cudaEventDisableTiming);
    }

    constexpr int WELEMS = E * H * IM;          // = E*IM*H

    // fork: weight fp32->fp16 conversion runs concurrently with attention path
    cudaEventRecord(evFork, 0);
    cudaStreamWaitEvent(s2, evFork, 0);
    wconv_k<<<WELEMS / 8 / 256, 256, 0, s2>>>(Wgate, 0);
    wconv_k<<<WELEMS / 8 / 256, 256, 0, s2>>>(Wup,   1);
    wconv_k<<<WELEMS / 8 / 256, 256, 0, s2>>>(Wdown, 2);
    cudaEventRecord(evJoin, s2);

    // main pipeline (default stream)
    rmsnorm_k<<<S, 256>>>(hidden, -1, ln1_g, 0, 0);
    dense_tf32<<<dim3(48, S / 128), 256>>>(0, Wq, Wk, Wv, nullptr, 0, H);
    attn_k<<<dim3(S / 64, NH), 256>>>();
    dense_tf32<<<dim3(32, S / 128), 256>>>(4, Wo, nullptr, nullptr, hidden, 1, NH * D);
    rmsnorm_k<<<S, 256>>>(nullptr, 5, ln2_g, 6, 1);   // also writes g_hnorm16
    zero_cnt_k<<<1, 64>>>();
    router_k<<<S, 64>>>(Wg);
    offsets_k<<<1, 1>>>();
    scatter_k<<<(NA + 255) / 256, 256>>>();

    // join: MoE needs the fp16 weights
    cudaStreamWaitEvent(0, evJoin, 0);

    moe_gu_f16<<<dim3(24, 128), 256>>>();
    swiglu_k<<<NA * IM / 2 / 256, 256>>>();
    moe_down_f16<<<dim3(32, 128), 256>>>();
    finalize_k<<<(S * H) / 256, 256>>>(out);
    (void)in_sizes; (void)n_in; (void)out_size;
}

// round 16
// speedup vs baseline: 1.1741x; 1.0518x over previous
#include <cuda_runtime.h>
#include <cuda_fp16.h>
#include <math.h>

// Problem constants
constexpr int S   = 1024;   // tokens
constexpr int H   = 2048;   // hidden
constexpr int NH  = 16;     // q heads
constexpr int NKV = 4;      // kv heads
constexpr int D   = 128;    // head dim
constexpr int E   = 64;     // experts
constexpr int TK  = 8;      // top_k
constexpr int IM  = 768;    // moe intermediate
constexpr float EPS = 1e-6f;
constexpr int NA = S * TK;  // total assignments = 8192

// dense GEMM tiling (128x128 CTA tile)
constexpr int KC   = 16;    // dense K-chunk
constexpr int AST  = 20;    // dense A smem stride (floats)
constexpr int BSTW = 136;   // dense B smem stride (floats, 128-wide tile)
// MoE fp16 tiling
constexpr int MKC  = 32;    // MoE K-chunk (halves)
constexpr int HST  = 40;    // A smem stride (halves)
constexpr int BSH  = 72;    // gu B smem stride (halves, 64-wide)
constexpr int BSHW = 136;   // down B smem stride (halves, 128-wide)
constexpr int MAXT = 200;   // worklist capacity

// ---------------- scratch ----------------
__device__ float g_xnorm [S * H];
__device__ float g_q     [S * NH * D];
__device__ float g_k     [S * NKV * D];
__device__ float g_v     [S * NKV * D];
__device__ float g_ctx   [S * NH * D];
__device__ float g_hid2  [S * H];
__device__ float g_hnorm [S * H];
__device__ __half g_hnorm16[S * H];
__device__ int   g_topk_id[NA];
__device__ float g_topk_w [NA];
__device__ int   g_cnt   [E];
__device__ int   g_off   [E + 1];
__device__ int   g_cur   [E];
__device__ int   g_tok   [NA];
__device__ float g_ew    [NA];
__device__ int   g_pos   [NA];
__device__ int   g_ntile;
__device__ int   g_te    [MAXT];
__device__ int   g_tt    [MAXT];
__device__ __half g_gate16[NA * IM];
__device__ __half g_up16  [NA * IM];
__device__ __half g_act16 [NA * IM];
__device__ float  g_part  [(size_t)NA * H];
__device__ __align__(16) __half g_w16G[(size_t)E * H * IM];
__device__ __align__(16) __half g_w16U[(size_t)E * H * IM];
__device__ __align__(16) __half g_w16D[(size_t)E * IM * H];

__device__ __forceinline__ float* bufptr(int b) {
    switch (b) {
        case 0: return g_xnorm;
        case 4: return g_ctx;
        case 5: return g_hid2;
        case 6: return g_hnorm;
    }
    return nullptr;
}

// ---------------- helpers ----------------
__device__ __forceinline__ unsigned smaddr(const void* p) {
    return (unsigned)__cvta_generic_to_shared(p);
}
__device__ __forceinline__ unsigned cvt_tf32(float f) {
    unsigned u; asm("cvt.rna.tf32.f32 %0, %1;" : "=r"(u) : "f"(f)); return u;
}
__device__ __forceinline__ void cpa16(unsigned s, const void* g) {
    asm volatile("cp.async.ca.shared.global [%0], [%1], 16;" :: "r"(s), "l"(g));
}
__device__ __forceinline__ void cp_commit() { asm volatile("cp.async.commit_group;"); }
__device__ __forceinline__ void cp_wait0()  { asm volatile("cp.async.wait_group 0;"); }
__device__ __forceinline__ void cp_wait1()  { asm volatile("cp.async.wait_group 1;"); }
__device__ __forceinline__ void ldsm_x4(unsigned r[4], unsigned a) {
    asm volatile("ldmatrix.sync.aligned.m8n8.x4.shared.b16 {%0,%1,%2,%3}, [%4];"
        : "=r"(r[0]), "=r"(r[1]), "=r"(r[2]), "=r"(r[3]) : "r"(a));
}
__device__ __forceinline__ void ldsm_x4_t(unsigned r[4], unsigned a) {
    asm volatile("ldmatrix.sync.aligned.m8n8.x4.trans.shared.b16 {%0,%1,%2,%3}, [%4];"
        : "=r"(r[0]), "=r"(r[1]), "=r"(r[2]), "=r"(r[3]) : "r"(a));
}
__device__ __forceinline__ void mma_tf32(float c[4], const unsigned a[4], const unsigned b[2]) {
    asm volatile(
        "mma.sync.aligned.m16n8k8.row.col.f32.tf32.tf32.f32 "
        "{%0,%1,%2,%3}, {%4,%5,%6,%7}, {%8,%9}, {%0,%1,%2,%3};\n"
        : "+f"(c[0]), "+f"(c[1]), "+f"(c[2]), "+f"(c[3])
        : "r"(a[0]), "r"(a[1]), "r"(a[2]), "r"(a[3]), "r"(b[0]), "r"(b[1]));
}
__device__ __forceinline__ void mma_f16(float c[4], const unsigned a[4], const unsigned b[2]) {
    asm volatile(
        "mma.sync.aligned.m16n8k16.row.col.f32.f16.f16.f32 "
        "{%0,%1,%2,%3}, {%4,%5,%6,%7}, {%8,%9}, {%0,%1,%2,%3};\n"
        : "+f"(c[0]), "+f"(c[1]), "+f"(c[2]), "+f"(c[3])
        : "r"(a[0]), "r"(a[1]), "r"(a[2]), "r"(a[3]), "r"(b[0]), "r"(b[1]));
}

// ---------------- RMSNorm (optionally also writes fp16 copy) ---------------
__global__ void rmsnorm_k(const float* __restrict__ x_ext, int xBuf,
                          const float* __restrict__ g, int outBuf, int alsoHalf) {
    const float* x = x_ext ? x_ext : bufptr(xBuf);
    float* out = bufptr(outBuf);
    int row = blockIdx.x, tid = threadIdx.x;
    const float* xr = x + (size_t)row * H;
    float ss = 0.f;
    for (int j = tid; j < H; j += 256) { float v = xr[j]; ss += v * v; }
    for (int o = 16; o; o >>= 1) ss += __shfl_xor_sync(0xffffffffu, ss, o);
    __shared__ float red[8];
    if ((tid & 31) == 0) red[tid >> 5] = ss;
    __syncthreads();
    if (tid < 32) {
        float v = (tid < 8) ? red[tid] : 0.f;
        for (int o = 4; o; o >>= 1) v += __shfl_xor_sync(0xffffffffu, v, o);
        if (tid == 0) red[0] = v;
    }
    __syncthreads();
    float inv = rsqrtf(red[0] / (float)H + EPS);
    for (int j = tid; j < H; j += 256) {
        float r = xr[j] * inv * g[j];
        out[(size_t)row * H + j] = r;
        if (alsoHalf) g_hnorm16[(size_t)row * H + j] = __float2half(r);
    }
}

// ---------------- weight fp32 -> fp16 convert ------------------------------
__global__ void wconv_k(const float* __restrict__ W, int dstSel) {
    __half* dst = (dstSel == 0) ? g_w16G : (dstSel == 1) ? g_w16U : g_w16D;
    size_t i8 = (size_t)blockIdx.x * 256 + threadIdx.x;
    const float4* src = (const float4*)W + i8 * 2;
    float4 a = src[0], b = src[1];
    __half2 h0 = __floats2half2_rn(a.x, a.y);
    __half2 h1 = __floats2half2_rn(a.z, a.w);
    __half2 h2 = __floats2half2_rn(b.x, b.y);
    __half2 h3 = __floats2half2_rn(b.z, b.w);
    uint4 o;
    o.x = *(unsigned*)&h0; o.y = *(unsigned*)&h1;
    o.z = *(unsigned*)&h2; o.w = *(unsigned*)&h3;
    ((uint4*)dst)[i8] = o;
}

// ---------------- dense TF32 GEMM, 128x128 CTA tile ------------------------
// 8 warps (4m x 2n), warp tile 32x64. mode 0: fused QKV (N=3072), mode 1: Wo.
__global__ __launch_bounds__(256) void dense_tf32(int aBuf,
        const float* __restrict__ W0, const float* __restrict__ W1,
        const float* __restrict__ W2, const float* __restrict__ res,
        int mode, int K) {
    const float* A = bufptr(aBuf);
    int m0 = blockIdx.y * 128;
    int n0c = blockIdx.x * 128;
    const float* B; int ldb, nb; float* Cp; int ldo;
    if (mode == 0) {
        if (n0c < 2048)      { B = W0; ldb = 2048; nb = n0c;        Cp = g_q; ldo = 2048; }
        else if (n0c < 2560) { B = W1; ldb = 512;  nb = n0c - 2048; Cp = g_k; ldo = 512; }
        else                 { B = W2; ldb = 512;  nb = n0c - 2560; Cp = g_v; ldo = 512; }
    } else { B = W0; ldb = 2048; nb = n0c; Cp = g_hid2; ldo = 2048; }
    __shared__ __align__(16) float As[2][128 * AST];
    __shared__ __align__(16) float Bs[2][KC * BSTW];
    int tid = threadIdx.x, lane = tid & 31, wid = tid >> 5;
    int wm = wid >> 1, wn = wid & 1;

    auto load_chunk = [&](int k0, int buf) {
        #pragma unroll
        for (int i = 0; i < 2; i++) {
            int id = tid + i * 256;
            int row = id >> 2, q = (id & 3) * 4;
            cpa16(smaddr(&As[buf][row * AST + q]),
                  A + (size_t)(m0 + row) * K + k0 + q);
        }
        #pragma unroll
        for (int i = 0; i < 2; i++) {
            int id = tid + i * 256;
            int kr = id >> 5, nc = (id & 31) * 4;
            cpa16(smaddr(&Bs[buf][kr * BSTW + nc]),
                  B + (size_t)(k0 + kr) * ldb + nb + nc);
        }
        cp_commit();
    };

    float acc[2][8][4] = {};
    int NCH = K / KC;
    load_chunk(0, 0);
    for (int c = 0; c < NCH; c++) {
        int buf = c & 1;
        if (c + 1 < NCH) { load_chunk((c + 1) * KC, buf ^ 1); cp_wait1(); }
        else             { cp_wait0(); }
        __syncthreads();
        #pragma unroll
        for (int ks = 0; ks < 2; ks++) {
            int kk = ks * 8;
            unsigned Af[2][4];
            #pragma unroll
            for (int m = 0; m < 2; m++) {
                const float* ap = &As[buf][(wm * 32 + m * 16 + (lane >> 2)) * AST + kk + (lane & 3)];
                Af[m][0] = cvt_tf32(ap[0]);
                Af[m][1] = cvt_tf32(ap[8 * AST]);
                Af[m][2] = cvt_tf32(ap[4]);
                Af[m][3] = cvt_tf32(ap[8 * AST + 4]);
            }
            #pragma unroll
            for (int nt = 0; nt < 8; nt++) {
                const float* bp = &Bs[buf][(kk + (lane & 3)) * BSTW + wn * 64 + nt * 8 + (lane >> 2)];
                unsigned Bf[2] = { cvt_tf32(bp[0]), cvt_tf32(bp[4 * BSTW]) };
                #pragma unroll
                for (int m = 0; m < 2; m++) mma_tf32(acc[m][nt], Af[m], Bf);
            }
        }
        __syncthreads();
    }
    #pragma unroll
    for (int m = 0; m < 2; m++)
        #pragma unroll
        for (int nt = 0; nt < 8; nt++)
            #pragma unroll
            for (int r = 0; r < 4; r++) {
                int row = m0 + wm * 32 + m * 16 + (lane >> 2) + ((r >= 2) ? 8 : 0);
                int col = wn * 64 + nt * 8 + (lane & 3) * 2 + (r & 1);
                size_t oidx = (size_t)row * ldo + nb + col;
                float v = acc[m][nt][r];
                if (res) v += res[oidx];
                Cp[oidx] = v;
            }
}

// ---------------- causal flash attention (fp32) ----------------
__global__ __launch_bounds__(256) void attn_k() {
    constexpr int KT = 32;
    constexpr float SC = 0.0883883476483184f;
    int qt = blockIdx.x, h = blockIdx.y;
    int kvh = h / (NH / NKV);
    int tid = threadIdx.x;
    int qi = tid >> 2, qr = tid & 3;
    int qrow = qt * 64 + qi;
    int d0 = qr * 32;
    __shared__ float Ks[KT][D];
    __shared__ float Vs[KT][D];
    float qreg[32], acc[32];
    #pragma unroll
    for (int d = 0; d < 32; d++) {
        qreg[d] = g_q[(size_t)qrow * (NH * D) + h * D + d0 + d] * SC;
        acc[d] = 0.f;
    }
    float m = -1e30f, l = 0.f;
    int ktiles = qt * 2 + 2;
    for (int kt = 0; kt < ktiles; kt++) {
        int kb = kt * KT;
        for (int idx = tid; idx < KT * D; idx += 256) {
            int r = idx >> 7, c = idx & 127;
            Ks[r][c] = g_k[(size_t)(kb + r) * (NKV * D) + kvh * D + c];
            Vs[r][c] = g_v[(size_t)(kb + r) * (NKV * D) + kvh * D + c];
        }
        __syncthreads();
        float sc[KT];
        #pragma unroll
        for (int j = 0; j < KT; j++) {
            float p = 0.f;
            #pragma unroll
            for (int d = 0; d < 32; d++) p += qreg[d] * Ks[j][d0 + d];
            p += __shfl_xor_sync(0xffffffffu, p, 1);
            p += __shfl_xor_sync(0xffffffffu, p, 2);
            sc[j] = (kb + j <= qrow) ? p : -1e30f;
        }
        float tm = m;
        #pragma unroll
        for (int j = 0; j < KT; j++) tm = fmaxf(tm, sc[j]);
        float corr = __expf(m - tm);
        m = tm;
        l *= corr;
        #pragma unroll
        for (int d = 0; d < 32; d++) acc[d] *= corr;
        #pragma unroll
        for (int j = 0; j < KT; j++) {
            float p = __expf(sc[j] - m);
            l += p;
            #pragma unroll
            for (int d = 0; d < 32; d++) acc[d] += p * Vs[j][d0 + d];
        }
        __syncthreads();
    }
    float inv = 1.f / l;
    #pragma unroll
    for (int d = 0; d < 32; d++)
        g_ctx[(size_t)qrow * (NH * D) + h * D + d0 + d] = acc[d] * inv;
}

// ---------------- router ----------------
__global__ void zero_cnt_k() { if (threadIdx.x < E) g_cnt[threadIdx.x] = 0; }

__global__ void router_k(const float* __restrict__ Wg) {
    int t = blockIdx.x, tid = threadIdx.x;   // blockDim = 64
    __shared__ float sh[H];
    __shared__ float lg[E];
    for (int j = tid; j < H; j += 64) sh[j] = g_hnorm[(size_t)t * H + j];
    __syncthreads();
    float lo = 0.f;
    for (int j = 0; j < H; j++) lo += sh[j] * Wg[(size_t)j * E + tid];
    lg[tid] = lo;
    __syncthreads();
    if (tid == 0) {
        float tmp[E];
        for (int e = 0; e < E; e++) tmp[e] = lg[e];
        int   id[TK]; float w[TK];
        for (int k = 0; k < TK; k++) {
            int best = 0; float bv = tmp[0];
            for (int e = 1; e < E; e++) if (tmp[e] > bv) { bv = tmp[e]; best = e; }
            id[k] = best; w[k] = bv; tmp[best] = -1e30f;
        }
        float mx = w[0], s = 0.f;
        for (int k = 0; k < TK; k++) { w[k] = expf(w[k] - mx); s += w[k]; }
        float inv = 1.f / s;
        for (int k = 0; k < TK; k++) {
            g_topk_id[t * TK + k] = id[k];
            g_topk_w [t * TK + k] = w[k] * inv;
            atomicAdd(&g_cnt[id[k]], 1);
        }
    }
}

__global__ void offsets_k() {
    if (threadIdx.x == 0) {
        int run = 0;
        for (int e = 0; e < E; e++) { g_off[e] = run; g_cur[e] = run; run += g_cnt[e]; }
        g_off[E] = run;
        int nt = 0;
        for (int e = 0; e < E; e++) {
            int cnt = g_off[e + 1] - g_off[e];
            for (int t0 = 0; t0 < cnt; t0 += 128) {
                g_te[nt] = e; g_tt[nt] = t0; nt++;
            }
        }
        g_ntile = nt;
    }
}

__global__ void scatter_k() {
    int a = blockIdx.x * blockDim.x + threadIdx.x;
    if (a < NA) {
        int e = g_topk_id[a];
        int pos = atomicAdd(&g_cur[e], 1);
        g_tok[pos] = a >> 3;
        g_ew [pos] = g_topk_w[a];
        g_pos[a]   = pos;
    }
}

// ---------------- MoE gate+up FUSED fp16 GEMM (one A stream, two B) --------
// grid (12, 128): x = n-tile (IM/64), y = worklist tile. CTA tile 128 x 64 x2.
__global__ __launch_bounds__(256) void moe_gu_f16() {
    int ti = blockIdx.y;
    if (ti >= g_ntile) return;
    int e = g_te[ti], t0 = g_tt[ti];
    int base = g_off[e], cnt = g_off[e + 1] - base;
    int i0 = blockIdx.x * 64;
    const __half* WG = g_w16G + (size_t)e * H * IM;
    const __half* WU = g_w16U + (size_t)e * H * IM;
    __shared__ __align__(16) __half As[2][128 * HST];
    __shared__ __align__(16) __half Bg[2][MKC * BSH];
    __shared__ __align__(16) __half Bu[2][MKC * BSH];
    __shared__ int stok[128];
    int tid = threadIdx.x, lane = tid & 31, wid = tid >> 5;
    int wm = wid >> 1, wn = wid & 1;
    int lg = lane >> 3, lr8 = lane & 7;
    if (tid < 128) {
        int r = t0 + tid;
        stok[tid] = (r < cnt) ? g_tok[base + r] : g_tok[base];
    }
    __syncthreads();

    auto load_chunk = [&](int k0, int buf) {
        #pragma unroll
        for (int i = 0; i < 2; i++) {
            int id = tid + i * 256;
            int row = id >> 2, q = (id & 3) * 8;
            cpa16(smaddr(&As[buf][row * HST + q]),
                  g_hnorm16 + (size_t)stok[row] * H + k0 + q);
        }
        int kr = tid >> 3, q = (tid & 7) * 8;
        cpa16(smaddr(&Bg[buf][kr * BSH + q]), WG + (size_t)(k0 + kr) * IM + i0 + q);
        cpa16(smaddr(&Bu[buf][kr * BSH + q]), WU + (size_t)(k0 + kr) * IM + i0 + q);
        cp_commit();
    };

    float accg[2][4][4] = {};
    float accu[2][4][4] = {};
    constexpr int NCH = H / MKC;   // 64
    load_chunk(0, 0);
    for (int c = 0; c < NCH; c++) {
        int buf = c & 1;
        if (c + 1 < NCH) { load_chunk((c + 1) * MKC, buf ^ 1); cp_wait1(); }
        else             { cp_wait0(); }
        __syncthreads();
        #pragma unroll
        for (int ks = 0; ks < 2; ks++) {
            int kk = ks * 16;
            unsigned Af[2][4];
            #pragma unroll
            for (int m = 0; m < 2; m++) {
                int row = wm * 32 + m * 16 + lr8 + (lg & 1) * 8;
                int col = kk + (lg >> 1) * 8;
                ldsm_x4(Af[m], smaddr(&As[buf][row * HST + col]));
            }
            #pragma unroll
            for (int np = 0; np < 2; np++) {
                int brow = kk + lr8 + (lg & 1) * 8;
                int bcol = wn * 32 + np * 16 + (lg >> 1) * 8;
                unsigned Gf[4], Uf[4];
                ldsm_x4_t(Gf, smaddr(&Bg[buf][brow * BSH + bcol]));
                ldsm_x4_t(Uf, smaddr(&Bu[buf][brow * BSH + bcol]));
                #pragma unroll
                for (int m = 0; m < 2; m++) {
                    mma_f16(accg[m][np * 2 + 0], Af[m], Gf + 0);
                    mma_f16(accg[m][np * 2 + 1], Af[m], Gf + 2);
                    mma_f16(accu[m][np * 2 + 0], Af[m], Uf + 0);
                    mma_f16(accu[m][np * 2 + 1], Af[m], Uf + 2);
                }
            }
        }
        __syncthreads();
    }
    #pragma unroll
    for (int m = 0; m < 2; m++)
        #pragma unroll
        for (int ng = 0; ng < 4; ng++) {
            int rr = wm * 32 + m * 16 + (lane >> 2);
            int colb = wn * 32 + ng * 8 + (lane & 3) * 2;
            if (t0 + rr < cnt) {
                size_t o = (size_t)(base + t0 + rr) * IM + i0 + colb;
                *(__half2*)&g_gate16[o] = __floats2half2_rn(accg[m][ng][0], accg[m][ng][1]);
                *(__half2*)&g_up16[o]   = __floats2half2_rn(accu[m][ng][0], accu[m][ng][1]);
            }
            if (t0 + rr + 8 < cnt) {
                size_t o = (size_t)(base + t0 + rr + 8) * IM + i0 + colb;
                *(__half2*)&g_gate16[o] = __floats2half2_rn(accg[m][ng][2], accg[m][ng][3]);
                *(__half2*)&g_up16[o]   = __floats2half2_rn(accu[m][ng][2], accu[m][ng][3]);
            }
        }
}

// ---------------- SwiGLU + combine-weight ----------------------------------
__global__ void swiglu_k() {
    int i2 = blockIdx.x * 256 + threadIdx.x;
    int p = i2 / (IM / 2);
    float w = g_ew[p];
    __half2 g2 = ((const __half2*)g_gate16)[i2];
    __half2 u2 = ((const __half2*)g_up16)[i2];
    float gx = __low2float(g2), gy = __high2float(g2);
    float ux = __low2float(u2), uy = __high2float(u2);
    float ax = (gx / (1.f + __expf(-gx))) * ux * w;
    float ay = (gy / (1.f + __expf(-gy))) * uy * w;
    ((__half2*)g_act16)[i2] = __floats2half2_rn(ax, ay);
}

// ---------------- MoE down fp16 GEMM, 128x128 tile -------------------------
// grid (16, 128). 8 warps (4m x 2n), warp 32x64.
__global__ __launch_bounds__(256) void moe_down_f16() {
    int ti = blockIdx.y;
    if (ti >= g_ntile) return;
    int e = g_te[ti], t0 = g_tt[ti];
    int base = g_off[e], cnt = g_off[e + 1] - base;
    int h0 = blockIdx.x * 128;
    __shared__ __align__(16) __half As[2][128 * HST];
    __shared__ __align__(16) __half Bs[2][MKC * BSHW];
    int tid = threadIdx.x, lane = tid & 31, wid = tid >> 5;
    int wm = wid >> 1, wn = wid & 1;
    int lg = lane >> 3, lr8 = lane & 7;
    const __half* W16 = g_w16D + (size_t)e * IM * H;

    auto load_chunk = [&](int k0, int buf) {
        #pragma unroll
        for (int i = 0; i < 2; i++) {
            int id = tid + i * 256;
            int row = id >> 2, q = (id & 3) * 8;
            int gr = t0 + row; if (gr >= cnt) gr = cnt - 1;
            cpa16(smaddr(&As[buf][row * HST + q]),
                  g_act16 + (size_t)(base + gr) * IM + k0 + q);
        }
        #pragma unroll
        for (int i = 0; i < 2; i++) {
            int id = tid + i * 256;
            int kr = id >> 4, q = (id & 15) * 8;
            cpa16(smaddr(&Bs[buf][kr * BSHW + q]),
                  W16 + (size_t)(k0 + kr) * H + h0 + q);
        }
        cp_commit();
    };

    float acc[2][8][4] = {};
    constexpr int NCH = IM / MKC;   // 24
    load_chunk(0, 0);
    for (int c = 0; c < NCH; c++) {
        int buf = c & 1;
        if (c + 1 < NCH) { load_chunk((c + 1) * MKC, buf ^ 1); cp_wait1(); }
        else             { cp_wait0(); }
        __syncthreads();
        #pragma unroll
        for (int ks = 0; ks < 2; ks++) {
            int kk = ks * 16;
            unsigned Af[2][4];
            #pragma unroll
            for (int m = 0; m < 2; m++) {
                int row = wm * 32 + m * 16 + lr8 + (lg & 1) * 8;
                int col = kk + (lg >> 1) * 8;
                ldsm_x4(Af[m], smaddr(&As[buf][row * HST + col]));
            }
            #pragma unroll
            for (int np = 0; np < 4; np++) {
                int brow = kk + lr8 + (lg & 1) * 8;
                int bcol = wn * 64 + np * 16 + (lg >> 1) * 8;
                unsigned Bf[4];
                ldsm_x4_t(Bf, smaddr(&Bs[buf][brow * BSHW + bcol]));
                #pragma unroll
                for (int m = 0; m < 2; m++) {
                    mma_f16(acc[m][np * 2 + 0], Af[m], Bf + 0);
                    mma_f16(acc[m][np * 2 + 1], Af[m], Bf + 2);
                }
            }
        }
        __syncthreads();
    }
    #pragma unroll
    for (int m = 0; m < 2; m++)
        #pragma unroll
        for (int ng = 0; ng < 8; ng++) {
            int rr = wm * 32 + m * 16 + (lane >> 2);
            int colb = wn * 64 + ng * 8 + (lane & 3) * 2;
            if (t0 + rr < cnt)
                *(float2*)&g_part[(size_t)(base + t0 + rr) * H + h0 + colb] =
                    make_float2(acc[m][ng][0], acc[m][ng][1]);
            if (t0 + rr + 8 < cnt)
                *(float2*)&g_part[(size_t)(base + t0 + rr + 8) * H + h0 + colb] =
                    make_float2(acc[m][ng][2], acc[m][ng][3]);
        }
}

// ---------------- finalize ----------------
__global__ void finalize_k(float* __restrict__ out) {
    size_t idx = (size_t)blockIdx.x * 256 + threadIdx.x;
    int t = (int)(idx >> 11);
    int hc = (int)(idx & 2047);
    float v = g_hid2[idx];
    #pragma unroll
    for (int k = 0; k < TK; k++)
        v += g_part[(size_t)g_pos[t * TK + k] * H + hc];
    out[idx] = v;
}

// ---------------- launch ----------------
extern "C" void kernel_launch(void* const* d_in, const int* in_sizes, int n_in,
                              void* d_out, int out_size) {
    const float* hidden = (const float*)d_in[0];
    const float* ln1_g  = (const float*)d_in[1];
    const float* ln2_g  = (const float*)d_in[2];
    const float* Wq     = (const float*)d_in[3];
    const float* Wk     = (const float*)d_in[4];
    const float* Wv     = (const float*)d_in[5];
    const float* Wo     = (const float*)d_in[6];
    const float* Wg     = (const float*)d_in[7];
    const float* Wgate  = (const float*)d_in[8];
    const float* Wup    = (const float*)d_in[9];
    const float* Wdown  = (const float*)d_in[10];
    float* out = (float*)d_out;

    static cudaStream_t s2 = nullptr;
    static cudaEvent_t evFork = nullptr, evJoin = nullptr;
    if (!s2) {
        cudaStreamCreateWithFlags(&s2, cudaStreamNonBlocking);
        cudaEventCreateWithFlags(&evFork, cudaEventDisableTiming);
        cudaEventCreateWithFlags(&evJoin, cudaEventDisableTiming);
    }

    constexpr int WELEMS = E * H * IM;

    // fork: weight conversion on side stream
    cudaEventRecord(evFork, 0);
    cudaStreamWaitEvent(s2, evFork, 0);
    wconv_k<<<WELEMS / 8 / 256, 256, 0, s2>>>(Wgate, 0);
    wconv_k<<<WELEMS / 8 / 256, 256, 0, s2>>>(Wup,   1);
    wconv_k<<<WELEMS / 8 / 256, 256, 0, s2>>>(Wdown, 2);
    cudaEventRecord(evJoin, s2);

    // main pipeline
    rmsnorm_k<<<S, 256>>>(hidden, -1, ln1_g, 0, 0);
    dense_tf32<<<dim3(24, S / 128), 256>>>(0, Wq, Wk, Wv, nullptr, 0, H);
    attn_k<<<dim3(S / 64, NH), 256>>>();
    dense_tf32<<<dim3(16, S / 128), 256>>>(4, Wo, nullptr, nullptr, hidden, 1, NH * D);
    rmsnorm_k<<<S, 256>>>(nullptr, 5, ln2_g, 6, 1);
    zero_cnt_k<<<1, 64>>>();
    router_k<<<S, 64>>>(Wg);
    offsets_k<<<1, 1>>>();
    scatter_k<<<(NA + 255) / 256, 256>>>();

    // join: MoE needs the fp16 weights
    cudaStreamWaitEvent(0, evJoin, 0);

    moe_gu_f16<<<dim3(12, 128), 256>>>();
    swiglu_k<<<NA * IM / 2 / 256, 256>>>();
    moe_down_f16<<<dim3(16, 128), 256>>>();
    finalize_k<<<(S * H) / 256, 256>>>(out);
    (void)in_sizes; (void)n_in; (void)out_size;
}